// round 4
// baseline (speedup 1.0000x reference)
#include <cuda_runtime.h>
#include <math.h>
#include <stdint.h>

#define BB 64
#define EE 1024
#define HH 1024
#define LL 512
#define VV 50257
#define NBLK_OUT 393   // ceil(VV/128)

// ---------------- scratch (device globals, no allocation) ----------------
__device__ float g_attnw[BB * LL];
__device__ float g_attnapp[BB * HH];
__device__ float g_x[BB * EE];
__device__ float g_partA[16 * BB * EE];      // attn 16*64*512, comb 16*64*1024, gi 4*64*3072
__device__ float g_partB[16 * BB * EE];      // gh 4*64*3072, attnapp 16*64*1024
__device__ float g_pmax[64 * 512];
__device__ float g_psum[64 * 512];
__device__ float g_lse[64];

// ---------------- helpers ----------------
__device__ __forceinline__ uint32_t pack_bf16(float lo, float hi) {
    uint32_t r;
    asm("cvt.rn.bf16x2.f32 %0, %1, %2;" : "=r"(r) : "f"(hi), "f"(lo));
    return r;
}
// 128B atoms: (8 rows x 8 k) bf16; XOR slotting for conflict-free ldmatrix
__device__ __forceinline__ int tile_off8(int row, int k) {
    int c = k >> 3;
    return (((row >> 3) << 3) + c) * 128 + (((row & 7) ^ c) << 4) + (k & 7) * 2;
}
// split fp32 -> (hi bf16 = truncated top16, lo bf16 = rn(a - hi)); store uint2 pairs
__device__ __forceinline__ void split_store(char* hiP, char* loP, int off, float4 v) {
    uint32_t bx = __float_as_uint(v.x), by = __float_as_uint(v.y);
    uint32_t bz = __float_as_uint(v.z), bw = __float_as_uint(v.w);
    uint2 hi = make_uint2(__byte_perm(bx, by, 0x7632), __byte_perm(bz, bw, 0x7632));
    float lx = v.x - __uint_as_float(bx & 0xffff0000u);
    float ly = v.y - __uint_as_float(by & 0xffff0000u);
    float lz = v.z - __uint_as_float(bz & 0xffff0000u);
    float lw = v.w - __uint_as_float(bw & 0xffff0000u);
    uint2 lo = make_uint2(pack_bf16(lx, ly), pack_bf16(lz, lw));
    *reinterpret_cast<uint2*>(hiP + off) = hi;
    *reinterpret_cast<uint2*>(loP + off) = lo;
}

#define MMA_BF16(ac, a, b0, b1)                                                   \
    asm volatile("mma.sync.aligned.m16n8k16.row.col.f32.bf16.bf16.f32 "           \
                 "{%0,%1,%2,%3}, {%4,%5,%6,%7}, {%8,%9}, {%0,%1,%2,%3};"          \
                 : "+f"((ac)[0]), "+f"((ac)[1]), "+f"((ac)[2]), "+f"((ac)[3])     \
                 : "r"((a)[0]), "r"((a)[1]), "r"((a)[2]), "r"((a)[3]),            \
                   "r"(b0), "r"(b1))

// ================= split-bf16 tensor GEMM (split-K partials) =================
// Cpart[s][64][N] = A[64, kChunk] @ W[N,K]^T.  BM=64 BN=128 BK=64, 256 thr.
__global__ __launch_bounds__(256) void gemm_bf16s(
    const float* __restrict__ A1, const float* __restrict__ A2,
    const int* __restrict__ gids, int K1, int K,
    const float* __restrict__ W, float* __restrict__ C, int N, int kChunk,
    const float* A1b, const float* Wb, float* Cb) {
    if (blockIdx.z == 1) { A1 = A1b; W = Wb; C = Cb; gids = nullptr; }

    __shared__ __align__(16) uint32_t smAhi[2048], smAlo[2048];  // 64x64 bf16 each
    __shared__ __align__(16) uint32_t smBhi[4096], smBlo[4096];  // 128x64 bf16 each

    const int tid = threadIdx.x;
    const int lane = tid & 31, wid = tid >> 5;
    const int wm = wid & 1, wn = wid >> 1;
    const int nBase = blockIdx.x * 128;
    const int kBase = blockIdx.y * kChunk;
    const int tiles = kChunk >> 6;

    uint32_t aHi = (uint32_t)__cvta_generic_to_shared(smAhi);
    uint32_t aLo = (uint32_t)__cvta_generic_to_shared(smAlo);
    uint32_t bHi = (uint32_t)__cvta_generic_to_shared(smBhi);
    uint32_t bLo = (uint32_t)__cvta_generic_to_shared(smBlo);

    int aAtom[2], aLowr[2];
#pragma unroll
    for (int ma = 0; ma < 2; ma++) {
        int row = wm * 32 + ma * 16 + ((lane >> 3) & 1) * 8 + (lane & 7);
        aAtom[ma] = (row >> 3) << 10;
        aLowr[ma] = row & 7;
    }
    const int aCbit = lane >> 4;
    int bAtom[4], bLowr[4];
    const int ll = lane & 15;
#pragma unroll
    for (int na = 0; na < 4; na++) {
        int n = wn * 32 + na * 8 + (ll & 7);
        bAtom[na] = (n >> 3) << 10;
        bLowr[na] = n & 7;
    }
    const int bCbit = ll >> 3;

    float acc[2][4][4];
#pragma unroll
    for (int i = 0; i < 2; i++)
#pragma unroll
        for (int j = 0; j < 4; j++)
#pragma unroll
            for (int q = 0; q < 4; q++) acc[i][j][q] = 0.f;

    float4 ra[4], rb[8];
    const int arow = tid >> 4, ac4 = tid & 15;

    auto loadA = [&](int k0) {
#pragma unroll
        for (int s = 0; s < 4; s++) {
            int row = arow + 16 * s;
            int k = k0 + ac4 * 4;
            const float* rp;
            if (k < K1) rp = (gids ? A1 + (size_t)gids[row] * K1 : A1 + (size_t)row * K1) + k;
            else        rp = A2 + (size_t)row * (K - K1) + (k - K1);
            ra[s] = *reinterpret_cast<const float4*>(rp);
        }
    };
    auto loadB = [&](int k0) {
#pragma unroll
        for (int s = 0; s < 8; s++)
            rb[s] = *reinterpret_cast<const float4*>(W + (size_t)(nBase + arow + 16 * s) * K + k0 + ac4 * 4);
    };

    loadA(kBase);
    loadB(kBase);

    for (int kt = 0; kt < tiles; kt++) {
        __syncthreads();
#pragma unroll
        for (int s = 0; s < 4; s++)
            split_store((char*)smAhi, (char*)smAlo, tile_off8(arow + 16 * s, ac4 * 4), ra[s]);
#pragma unroll
        for (int s = 0; s < 8; s++)
            split_store((char*)smBhi, (char*)smBlo, tile_off8(arow + 16 * s, ac4 * 4), rb[s]);
        __syncthreads();
        if (kt + 1 < tiles) {
            loadA(kBase + (kt + 1) * 64);
            loadB(kBase + (kt + 1) * 64);
        }
#pragma unroll
        for (int ka = 0; ka < 4; ka++) {
            uint32_t afh[2][4], afl[2][4], bfh[4][2], bfl[4][2];
#pragma unroll
            for (int ma = 0; ma < 2; ma++) {
                int c = ka * 2 + aCbit;
                uint32_t off = aAtom[ma] + c * 128 + ((aLowr[ma] ^ c) << 4);
                asm volatile("ldmatrix.sync.aligned.m8n8.x4.shared.b16 {%0,%1,%2,%3}, [%4];"
                             : "=r"(afh[ma][0]), "=r"(afh[ma][1]), "=r"(afh[ma][2]), "=r"(afh[ma][3])
                             : "r"(aHi + off));
                asm volatile("ldmatrix.sync.aligned.m8n8.x4.shared.b16 {%0,%1,%2,%3}, [%4];"
                             : "=r"(afl[ma][0]), "=r"(afl[ma][1]), "=r"(afl[ma][2]), "=r"(afl[ma][3])
                             : "r"(aLo + off));
            }
#pragma unroll
            for (int na = 0; na < 4; na++) {
                int c = ka * 2 + bCbit;
                uint32_t off = bAtom[na] + c * 128 + ((bLowr[na] ^ c) << 4);
                asm volatile("ldmatrix.sync.aligned.m8n8.x2.shared.b16 {%0,%1}, [%2];"
                             : "=r"(bfh[na][0]), "=r"(bfh[na][1]) : "r"(bHi + off));
                asm volatile("ldmatrix.sync.aligned.m8n8.x2.shared.b16 {%0,%1}, [%2];"
                             : "=r"(bfl[na][0]), "=r"(bfl[na][1]) : "r"(bLo + off));
            }
#pragma unroll
            for (int ma = 0; ma < 2; ma++)
#pragma unroll
                for (int na = 0; na < 4; na++) {
                    MMA_BF16(acc[ma][na], afh[ma], bfh[na][0], bfh[na][1]);
                    MMA_BF16(acc[ma][na], afh[ma], bfl[na][0], bfl[na][1]);
                    MMA_BF16(acc[ma][na], afl[ma], bfh[na][0], bfh[na][1]);
                }
        }
    }

    float* Cout = C + (size_t)blockIdx.y * 64 * N;
    int g = lane >> 2, tig = lane & 3;
#pragma unroll
    for (int ma = 0; ma < 2; ma++)
#pragma unroll
        for (int na = 0; na < 4; na++) {
            int col = nBase + wn * 32 + na * 8 + tig * 2;
            int r0 = wm * 32 + ma * 16 + g;
            *reinterpret_cast<float2*>(Cout + (size_t)r0 * N + col) =
                make_float2(acc[ma][na][0], acc[ma][na][1]);
            *reinterpret_cast<float2*>(Cout + (size_t)(r0 + 8) * N + col) =
                make_float2(acc[ma][na][2], acc[ma][na][3]);
        }
}

// ================= fat output GEMM (split-bf16) + bias + fused lsm partials =================
__global__ __launch_bounds__(256) void k_outproj(const float* __restrict__ A,
                                                 const float* __restrict__ W,
                                                 const float* __restrict__ bias,
                                                 float* __restrict__ C,
                                                 float* __restrict__ pmax,
                                                 float* __restrict__ psum) {
    __shared__ __align__(16) uint32_t smAhi[2048], smAlo[2048];
    __shared__ __align__(16) uint32_t smBhi[4096], smBlo[4096];
    __shared__ float redMax[64][4];
    __shared__ float redSum[64][4];

    const int tid = threadIdx.x;
    const int lane = tid & 31, wid = tid >> 5;
    const int wm = wid & 1, wn = wid >> 1;
    const int nBase = blockIdx.x * 128;

    uint32_t aHi = (uint32_t)__cvta_generic_to_shared(smAhi);
    uint32_t aLo = (uint32_t)__cvta_generic_to_shared(smAlo);
    uint32_t bHi = (uint32_t)__cvta_generic_to_shared(smBhi);
    uint32_t bLo = (uint32_t)__cvta_generic_to_shared(smBlo);

    int aAtom[2], aLowr[2];
#pragma unroll
    for (int ma = 0; ma < 2; ma++) {
        int row = wm * 32 + ma * 16 + ((lane >> 3) & 1) * 8 + (lane & 7);
        aAtom[ma] = (row >> 3) << 10;
        aLowr[ma] = row & 7;
    }
    const int aCbit = lane >> 4;
    int bAtom[4], bLowr[4];
    const int ll = lane & 15;
#pragma unroll
    for (int na = 0; na < 4; na++) {
        int n = wn * 32 + na * 8 + (ll & 7);
        bAtom[na] = (n >> 3) << 10;
        bLowr[na] = n & 7;
    }
    const int bCbit = ll >> 3;

    float acc[2][4][4];
#pragma unroll
    for (int i = 0; i < 2; i++)
#pragma unroll
        for (int j = 0; j < 4; j++)
#pragma unroll
            for (int q = 0; q < 4; q++) acc[i][j][q] = 0.f;

    float4 ra[4], rb[8];
    const int arow = tid >> 4, ac4 = tid & 15;

    auto loadA = [&](int k0) {
#pragma unroll
        for (int s = 0; s < 4; s++)
            ra[s] = *reinterpret_cast<const float4*>(A + (size_t)(arow + 16 * s) * 1024 + k0 + ac4 * 4);
    };
    auto loadB = [&](int k0) {
#pragma unroll
        for (int s = 0; s < 8; s++) {
            int ng = nBase + arow + 16 * s;
            if (ng < VV)
                rb[s] = *reinterpret_cast<const float4*>(W + (size_t)ng * 1024 + k0 + ac4 * 4);
            else
                rb[s] = make_float4(0.f, 0.f, 0.f, 0.f);
        }
    };

    loadA(0);
    loadB(0);

    for (int kt = 0; kt < 16; kt++) {
        __syncthreads();
#pragma unroll
        for (int s = 0; s < 4; s++)
            split_store((char*)smAhi, (char*)smAlo, tile_off8(arow + 16 * s, ac4 * 4), ra[s]);
#pragma unroll
        for (int s = 0; s < 8; s++)
            split_store((char*)smBhi, (char*)smBlo, tile_off8(arow + 16 * s, ac4 * 4), rb[s]);
        __syncthreads();
        if (kt + 1 < 16) {
            loadA((kt + 1) * 64);
            loadB((kt + 1) * 64);
        }
#pragma unroll
        for (int ka = 0; ka < 4; ka++) {
            uint32_t afh[2][4], afl[2][4], bfh[4][2], bfl[4][2];
#pragma unroll
            for (int ma = 0; ma < 2; ma++) {
                int c = ka * 2 + aCbit;
                uint32_t off = aAtom[ma] + c * 128 + ((aLowr[ma] ^ c) << 4);
                asm volatile("ldmatrix.sync.aligned.m8n8.x4.shared.b16 {%0,%1,%2,%3}, [%4];"
                             : "=r"(afh[ma][0]), "=r"(afh[ma][1]), "=r"(afh[ma][2]), "=r"(afh[ma][3])
                             : "r"(aHi + off));
                asm volatile("ldmatrix.sync.aligned.m8n8.x4.shared.b16 {%0,%1,%2,%3}, [%4];"
                             : "=r"(afl[ma][0]), "=r"(afl[ma][1]), "=r"(afl[ma][2]), "=r"(afl[ma][3])
                             : "r"(aLo + off));
            }
#pragma unroll
            for (int na = 0; na < 4; na++) {
                int c = ka * 2 + bCbit;
                uint32_t off = bAtom[na] + c * 128 + ((bLowr[na] ^ c) << 4);
                asm volatile("ldmatrix.sync.aligned.m8n8.x2.shared.b16 {%0,%1}, [%2];"
                             : "=r"(bfh[na][0]), "=r"(bfh[na][1]) : "r"(bHi + off));
                asm volatile("ldmatrix.sync.aligned.m8n8.x2.shared.b16 {%0,%1}, [%2];"
                             : "=r"(bfl[na][0]), "=r"(bfl[na][1]) : "r"(bLo + off));
            }
#pragma unroll
            for (int ma = 0; ma < 2; ma++)
#pragma unroll
                for (int na = 0; na < 4; na++) {
                    MMA_BF16(acc[ma][na], afh[ma], bfh[na][0], bfh[na][1]);
                    MMA_BF16(acc[ma][na], afh[ma], bfl[na][0], bfl[na][1]);
                    MMA_BF16(acc[ma][na], afl[ma], bfh[na][0], bfh[na][1]);
                }
        }
    }

    // epilogue: bias add, store C, per-row max/sumexp partials
    int g = lane >> 2, tig = lane & 3;
#pragma unroll
    for (int ma = 0; ma < 2; ma++)
#pragma unroll
        for (int na = 0; na < 4; na++) {
            int col = nBase + wn * 32 + na * 8 + tig * 2;
            int r0 = wm * 32 + ma * 16 + g;
            if (col < VV) {
                float b0 = bias[col];
                acc[ma][na][0] += b0; acc[ma][na][2] += b0;
                C[(size_t)r0 * VV + col]       = acc[ma][na][0];
                C[(size_t)(r0 + 8) * VV + col] = acc[ma][na][2];
            } else { acc[ma][na][0] = -1e30f; acc[ma][na][2] = -1e30f; }
            if (col + 1 < VV) {
                float b1 = bias[col + 1];
                acc[ma][na][1] += b1; acc[ma][na][3] += b1;
                C[(size_t)r0 * VV + col + 1]       = acc[ma][na][1];
                C[(size_t)(r0 + 8) * VV + col + 1] = acc[ma][na][3];
            } else { acc[ma][na][1] = -1e30f; acc[ma][na][3] = -1e30f; }
        }

#pragma unroll
    for (int ma = 0; ma < 2; ma++) {
        float m0 = -1e30f, m1 = -1e30f;
#pragma unroll
        for (int na = 0; na < 4; na++) {
            m0 = fmaxf(m0, fmaxf(acc[ma][na][0], acc[ma][na][1]));
            m1 = fmaxf(m1, fmaxf(acc[ma][na][2], acc[ma][na][3]));
        }
        m0 = fmaxf(m0, __shfl_xor_sync(~0u, m0, 1));
        m0 = fmaxf(m0, __shfl_xor_sync(~0u, m0, 2));
        m1 = fmaxf(m1, __shfl_xor_sync(~0u, m1, 1));
        m1 = fmaxf(m1, __shfl_xor_sync(~0u, m1, 2));
        if (tig == 0) {
            redMax[wm * 32 + ma * 16 + g][wn] = m0;
            redMax[wm * 32 + ma * 16 + g + 8][wn] = m1;
        }
    }
    __syncthreads();
#pragma unroll
    for (int ma = 0; ma < 2; ma++)
#pragma unroll
        for (int h = 0; h < 2; h++) {
            int row = wm * 32 + ma * 16 + g + h * 8;
            float rm = fmaxf(fmaxf(redMax[row][0], redMax[row][1]),
                             fmaxf(redMax[row][2], redMax[row][3]));
            float s = 0.f;
#pragma unroll
            for (int na = 0; na < 4; na++) {
                s += __expf(acc[ma][na][h * 2] - rm);
                s += __expf(acc[ma][na][h * 2 + 1] - rm);
            }
            s += __shfl_xor_sync(~0u, s, 1);
            s += __shfl_xor_sync(~0u, s, 2);
            if (tig == 0) redSum[row][wn] = s;
        }
    __syncthreads();
    if (tid < 64) {
        float rm = fmaxf(fmaxf(redMax[tid][0], redMax[tid][1]),
                         fmaxf(redMax[tid][2], redMax[tid][3]));
        float s = redSum[tid][0] + redSum[tid][1] + redSum[tid][2] + redSum[tid][3];
        pmax[tid * 512 + blockIdx.x] = rm;
        psum[tid * 512 + blockIdx.x] = s;
    }
}

// ---------------- attn logits reduce + softmax over L=512 ----------------
__global__ void k_attn_softmax(const float* __restrict__ part, const float* __restrict__ bias,
                               float* __restrict__ wout) {
    int b = blockIdx.x;
    int l = threadIdx.x;
    float v = bias[l];
#pragma unroll
    for (int s = 0; s < 16; s++) v += part[((size_t)s * BB + b) * LL + l];

    __shared__ float red[32];
    float m = v;
#pragma unroll
    for (int o = 16; o > 0; o >>= 1) m = fmaxf(m, __shfl_xor_sync(~0u, m, o));
    if ((threadIdx.x & 31) == 0) red[threadIdx.x >> 5] = m;
    __syncthreads();
    if (threadIdx.x < 32) {
        float t = (threadIdx.x < 16) ? red[threadIdx.x] : -1e30f;
#pragma unroll
        for (int o = 8; o > 0; o >>= 1) t = fmaxf(t, __shfl_xor_sync(~0u, t, o));
        if (threadIdx.x == 0) red[0] = t;
    }
    __syncthreads();
    float rowmax = red[0];
    __syncthreads();
    float e = expf(v - rowmax);
    float ssum = e;
#pragma unroll
    for (int o = 16; o > 0; o >>= 1) ssum += __shfl_xor_sync(~0u, ssum, o);
    if ((threadIdx.x & 31) == 0) red[threadIdx.x >> 5] = ssum;
    __syncthreads();
    if (threadIdx.x < 32) {
        float t = (threadIdx.x < 16) ? red[threadIdx.x] : 0.f;
#pragma unroll
        for (int o = 8; o > 0; o >>= 1) t += __shfl_xor_sync(~0u, t, o);
        if (threadIdx.x == 0) red[0] = t;
    }
    __syncthreads();
    wout[b * LL + l] = e / red[0];
}

// ---------------- attn context partials: 16 slices of 32 L-rows ----------------
__global__ void k_attnapp_part(const float* __restrict__ w, const float* __restrict__ enc,
                               float* __restrict__ part) {
    int s = blockIdx.x;
    int b = blockIdx.y;
    int d4 = threadIdx.x;
    __shared__ float ws[32];
    if (threadIdx.x < 32) ws[threadIdx.x] = w[b * LL + s * 32 + threadIdx.x];
    __syncthreads();
    const float4* ep = reinterpret_cast<const float4*>(enc + (size_t)b * LL * HH + (size_t)s * 32 * HH) + d4;
    float4 acc = make_float4(0.f, 0.f, 0.f, 0.f);
#pragma unroll 8
    for (int l = 0; l < 32; l++) {
        float4 v = ep[l * (HH / 4)];
        float c = ws[l];
        acc.x += c * v.x; acc.y += c * v.y; acc.z += c * v.z; acc.w += c * v.w;
    }
    reinterpret_cast<float4*>(part + ((size_t)s * BB + b) * HH)[d4] = acc;
}

__global__ void k_attnred(const float4* __restrict__ part, float4* __restrict__ out) {
    int i = blockIdx.x * 256 + threadIdx.x;      // over 16384 float4
    float4 v = make_float4(0.f, 0.f, 0.f, 0.f);
#pragma unroll
    for (int s = 0; s < 16; s++) {
        float4 p = part[(size_t)s * (BB * HH / 4) + i];
        v.x += p.x; v.y += p.y; v.z += p.z; v.w += p.w;
    }
    out[i] = v;
}

// ---------------- combine reduce + bias + relu ----------------
__global__ void k_combrelu(const float* __restrict__ part, const float* __restrict__ bias,
                           float* __restrict__ out) {
    int idx = blockIdx.x * 256 + threadIdx.x;
    int e = idx & (EE - 1);
    float v = bias[e];
#pragma unroll
    for (int s = 0; s < 16; s++) v += part[(size_t)s * BB * EE + idx];
    out[idx] = fmaxf(v, 0.f);
}

// ---------------- GRU gates (split 4) ----------------
__global__ void k_gru(const float* __restrict__ pgi, const float* __restrict__ pgh,
                      const float* __restrict__ bih, const float* __restrict__ bhh,
                      const float* __restrict__ hidden, float* __restrict__ newh) {
    int idx = blockIdx.x * 256 + threadIdx.x;
    int b = idx >> 10;
    int h = idx & 1023;
    const int N3 = 3 * HH;
    float ir = bih[h], iz = bih[HH + h], in_ = bih[2 * HH + h];
    float hr = bhh[h], hz = bhh[HH + h], hn = bhh[2 * HH + h];
#pragma unroll
    for (int s = 0; s < 4; s++) {
        size_t base = ((size_t)s * BB + b) * N3;
        ir  += pgi[base + h];
        iz  += pgi[base + HH + h];
        in_ += pgi[base + 2 * HH + h];
        hr  += pgh[base + h];
        hz  += pgh[base + HH + h];
        hn  += pgh[base + 2 * HH + h];
    }
    float r = 1.f / (1.f + expf(-(ir + hr)));
    float z = 1.f / (1.f + expf(-(iz + hz)));
    float n = tanhf(in_ + r * hn);
    newh[idx] = (1.f - z) * n + z * hidden[idx];
}

// ---------------- lsm combine + write ----------------
__global__ void k_lsm_comb(const float* __restrict__ pmax, const float* __restrict__ psum,
                           float* __restrict__ lse) {
    int row = blockIdx.x;
    __shared__ float red[32];
    float m = -1e30f;
    for (int c = threadIdx.x; c < NBLK_OUT; c += 128) m = fmaxf(m, pmax[row * 512 + c]);
#pragma unroll
    for (int o = 16; o > 0; o >>= 1) m = fmaxf(m, __shfl_xor_sync(~0u, m, o));
    if ((threadIdx.x & 31) == 0) red[threadIdx.x >> 5] = m;
    __syncthreads();
    if (threadIdx.x < 32) {
        float t = (threadIdx.x < 4) ? red[threadIdx.x] : -1e30f;
#pragma unroll
        for (int o = 2; o > 0; o >>= 1) t = fmaxf(t, __shfl_xor_sync(~0u, t, o));
        if (threadIdx.x == 0) red[0] = t;
    }
    __syncthreads();
    float M = red[0];
    __syncthreads();
    float s = 0.f;
    for (int c = threadIdx.x; c < NBLK_OUT; c += 128)
        s += psum[row * 512 + c] * __expf(pmax[row * 512 + c] - M);
#pragma unroll
    for (int o = 16; o > 0; o >>= 1) s += __shfl_xor_sync(~0u, s, o);
    if ((threadIdx.x & 31) == 0) red[threadIdx.x >> 5] = s;
    __syncthreads();
    if (threadIdx.x < 32) {
        float t = (threadIdx.x < 4) ? red[threadIdx.x] : 0.f;
#pragma unroll
        for (int o = 2; o > 0; o >>= 1) t += __shfl_xor_sync(~0u, t, o);
        if (threadIdx.x == 0) lse[row] = M + logf(t);
    }
}

__global__ void k_lsm_write(float* __restrict__ out, const float* __restrict__ lse) {
    int c = blockIdx.x;
    int b = blockIdx.y;
    const int CH = (VV + 7) / 8;
    int start = c * CH;
    int end = min(start + CH, VV);
    float L = lse[b];
    float* row = out + (size_t)b * VV;
    for (int i = start + threadIdx.x; i < end; i += 256) row[i] -= L;
}

// ---------------- launch ----------------
extern "C" void kernel_launch(void* const* d_in, const int* in_sizes, int n_in,
                              void* d_out, int out_size) {
    const int*   ids    = (const int*)  d_in[0];
    const float* hidden = (const float*)d_in[1];
    const float* enc    = (const float*)d_in[2];
    const float* embW   = (const float*)d_in[3];
    const float* attnW  = (const float*)d_in[4];
    const float* attnb  = (const float*)d_in[5];
    const float* combW  = (const float*)d_in[6];
    const float* combb  = (const float*)d_in[7];
    const float* Wih    = (const float*)d_in[8];
    const float* Whh    = (const float*)d_in[9];
    const float* bih    = (const float*)d_in[10];
    const float* bhh    = (const float*)d_in[11];
    const float* outW   = (const float*)d_in[12];
    const float* outb   = (const float*)d_in[13];

    float* out  = (float*)d_out;
    float* newh = out + (size_t)BB * VV;

    float *p_attnw, *p_attnapp, *p_x, *p_pa, *p_pb, *p_pmax, *p_psum, *p_lse;
    cudaGetSymbolAddress((void**)&p_attnw, g_attnw);
    cudaGetSymbolAddress((void**)&p_attnapp, g_attnapp);
    cudaGetSymbolAddress((void**)&p_x, g_x);
    cudaGetSymbolAddress((void**)&p_pa, g_partA);
    cudaGetSymbolAddress((void**)&p_pb, g_partB);
    cudaGetSymbolAddress((void**)&p_pmax, g_pmax);
    cudaGetSymbolAddress((void**)&p_psum, g_psum);
    cudaGetSymbolAddress((void**)&p_lse, g_lse);

    // 1. attn logits: cat(gather(emb), hidden) @ attn_W^T, split-K 16
    gemm_bf16s<<<dim3(4, 16, 1), 256>>>(embW, hidden, ids, EE, EE + HH, attnW,
                                        p_pa, LL, 128, nullptr, nullptr, nullptr);

    // 2. reduce + bias + softmax over L
    k_attn_softmax<<<BB, 512>>>(p_pa, attnb, p_attnw);

    // 3. attention context (16 L-slices + float4 reduce)
    k_attnapp_part<<<dim3(16, BB), 256>>>(p_attnw, enc, p_pb);
    k_attnred<<<64, 256>>>((const float4*)p_pb, (float4*)p_attnapp);

    // 4. combine: cat(gather(emb), attn_applied) @ comb_W^T, split-K 16
    gemm_bf16s<<<dim3(8, 16, 1), 256>>>(embW, p_attnapp, ids, EE, EE + HH, combW,
                                        p_pa, EE, 128, nullptr, nullptr, nullptr);
    k_combrelu<<<(BB * EE) / 256, 256>>>(p_pa, combb, p_x);

    // 5. GRU gi (z=0) and gh (z=1), split-K 4
    gemm_bf16s<<<dim3(24, 4, 2), 256>>>(p_x, nullptr, nullptr, HH, HH, Wih,
                                        p_pa, 3 * HH, 256,
                                        hidden, Whh, p_pb);
    k_gru<<<(BB * HH) / 256, 256>>>(p_pa, p_pb, bih, bhh, hidden, newh);

    // 6. output projection (split-bf16 tensor) + fused lsm partials
    k_outproj<<<NBLK_OUT, 256>>>(newh, outW, outb, out, p_pmax, p_psum);

    // 7. lsm combine + write
    k_lsm_comb<<<BB, 128>>>(p_pmax, p_psum, p_lse);
    k_lsm_write<<<dim3(8, BB), 256>>>(out, p_lse);
}

// round 5
// speedup vs baseline: 1.0837x; 1.0837x over previous
#include <cuda_runtime.h>
#include <math.h>
#include <stdint.h>

#define BB 64
#define EE 1024
#define HH 1024
#define LL 512
#define VV 50257
#define NBLK_OUT 393   // ceil(VV/128)

// ---------------- scratch (device globals, no allocation) ----------------
__device__ float g_attnw[BB * LL];
__device__ float g_attnapp[BB * HH];
__device__ float g_x[BB * EE];
__device__ float g_partA[16 * BB * EE];      // attn 16*64*512, red1 4*64*1024, comb 16*64*1024, gi 4*64*3072
__device__ float g_partB[16 * BB * EE];      // attnapp 16*64*1024, gh 4*64*3072
__device__ float g_pmax[64 * 512];
__device__ float g_psum[64 * 512];
__device__ float g_lse[64];

// ---------------- helpers ----------------
__device__ __forceinline__ uint32_t pack_bf16(float lo, float hi) {
    uint32_t r;
    asm("cvt.rn.bf16x2.f32 %0, %1, %2;" : "=r"(r) : "f"(hi), "f"(lo));
    return r;
}
// 128B atoms: (8 rows x 8 k) bf16; XOR slotting for conflict-free ldmatrix
__device__ __forceinline__ int tile_off8(int row, int k) {
    int c = k >> 3;
    return (((row >> 3) << 3) + c) * 128 + (((row & 7) ^ c) << 4) + (k & 7) * 2;
}
// split fp32 -> (hi bf16 = truncated top16, lo bf16 = rn(a - hi))
__device__ __forceinline__ void split_store(char* hiP, char* loP, int off, float4 v) {
    uint32_t bx = __float_as_uint(v.x), by = __float_as_uint(v.y);
    uint32_t bz = __float_as_uint(v.z), bw = __float_as_uint(v.w);
    uint2 hi = make_uint2(__byte_perm(bx, by, 0x7632), __byte_perm(bz, bw, 0x7632));
    float lx = v.x - __uint_as_float(bx & 0xffff0000u);
    float ly = v.y - __uint_as_float(by & 0xffff0000u);
    float lz = v.z - __uint_as_float(bz & 0xffff0000u);
    float lw = v.w - __uint_as_float(bw & 0xffff0000u);
    uint2 lo = make_uint2(pack_bf16(lx, ly), pack_bf16(lz, lw));
    *reinterpret_cast<uint2*>(hiP + off) = hi;
    *reinterpret_cast<uint2*>(loP + off) = lo;
}
__device__ __forceinline__ void rn_store(char* P, int off, float4 v) {
    uint2 r = make_uint2(pack_bf16(v.x, v.y), pack_bf16(v.z, v.w));
    *reinterpret_cast<uint2*>(P + off) = r;
}

#define MMA_BF16(ac, a, b0, b1)                                                   \
    asm volatile("mma.sync.aligned.m16n8k16.row.col.f32.bf16.bf16.f32 "           \
                 "{%0,%1,%2,%3}, {%4,%5,%6,%7}, {%8,%9}, {%0,%1,%2,%3};"          \
                 : "+f"((ac)[0]), "+f"((ac)[1]), "+f"((ac)[2]), "+f"((ac)[3])     \
                 : "r"((a)[0]), "r"((a)[1]), "r"((a)[2]), "r"((a)[3]),            \
                   "r"(b0), "r"(b1))

// ================= split-bf16 tensor GEMM (split-K partials, 3-MMA) =================
__global__ __launch_bounds__(256) void gemm_bf16s(
    const float* __restrict__ A1, const float* __restrict__ A2,
    const int* __restrict__ gids, int K1, int K,
    const float* __restrict__ W, float* __restrict__ C, int N, int kChunk,
    const float* A1b, const float* Wb, float* Cb) {
    if (blockIdx.z == 1) { A1 = A1b; W = Wb; C = Cb; gids = nullptr; }

    __shared__ __align__(16) uint32_t smAhi[2048], smAlo[2048];
    __shared__ __align__(16) uint32_t smBhi[4096], smBlo[4096];

    const int tid = threadIdx.x;
    const int lane = tid & 31, wid = tid >> 5;
    const int wm = wid & 1, wn = wid >> 1;
    const int nBase = blockIdx.x * 128;
    const int kBase = blockIdx.y * kChunk;
    const int tiles = kChunk >> 6;

    uint32_t aHi = (uint32_t)__cvta_generic_to_shared(smAhi);
    uint32_t aLo = (uint32_t)__cvta_generic_to_shared(smAlo);
    uint32_t bHi = (uint32_t)__cvta_generic_to_shared(smBhi);
    uint32_t bLo = (uint32_t)__cvta_generic_to_shared(smBlo);

    int aAtom[2], aLowr[2];
#pragma unroll
    for (int ma = 0; ma < 2; ma++) {
        int row = wm * 32 + ma * 16 + ((lane >> 3) & 1) * 8 + (lane & 7);
        aAtom[ma] = (row >> 3) << 10;
        aLowr[ma] = row & 7;
    }
    const int aCbit = lane >> 4;
    int bAtom[4], bLowr[4];
    const int ll = lane & 15;
#pragma unroll
    for (int na = 0; na < 4; na++) {
        int n = wn * 32 + na * 8 + (ll & 7);
        bAtom[na] = (n >> 3) << 10;
        bLowr[na] = n & 7;
    }
    const int bCbit = ll >> 3;

    float acc[2][4][4];
#pragma unroll
    for (int i = 0; i < 2; i++)
#pragma unroll
        for (int j = 0; j < 4; j++)
#pragma unroll
            for (int q = 0; q < 4; q++) acc[i][j][q] = 0.f;

    float4 ra[4], rb[8];
    const int arow = tid >> 4, ac4 = tid & 15;

    auto loadA = [&](int k0) {
#pragma unroll
        for (int s = 0; s < 4; s++) {
            int row = arow + 16 * s;
            int k = k0 + ac4 * 4;
            const float* rp;
            if (k < K1) rp = (gids ? A1 + (size_t)gids[row] * K1 : A1 + (size_t)row * K1) + k;
            else        rp = A2 + (size_t)row * (K - K1) + (k - K1);
            ra[s] = *reinterpret_cast<const float4*>(rp);
        }
    };
    auto loadB = [&](int k0) {
#pragma unroll
        for (int s = 0; s < 8; s++)
            rb[s] = *reinterpret_cast<const float4*>(W + (size_t)(nBase + arow + 16 * s) * K + k0 + ac4 * 4);
    };

    loadA(kBase);
    loadB(kBase);

    for (int kt = 0; kt < tiles; kt++) {
        __syncthreads();
#pragma unroll
        for (int s = 0; s < 4; s++)
            split_store((char*)smAhi, (char*)smAlo, tile_off8(arow + 16 * s, ac4 * 4), ra[s]);
#pragma unroll
        for (int s = 0; s < 8; s++)
            split_store((char*)smBhi, (char*)smBlo, tile_off8(arow + 16 * s, ac4 * 4), rb[s]);
        __syncthreads();
        if (kt + 1 < tiles) {
            loadA(kBase + (kt + 1) * 64);
            loadB(kBase + (kt + 1) * 64);
        }
#pragma unroll
        for (int ka = 0; ka < 4; ka++) {
            uint32_t afh[2][4], afl[2][4], bfh[4][2], bfl[4][2];
#pragma unroll
            for (int ma = 0; ma < 2; ma++) {
                int c = ka * 2 + aCbit;
                uint32_t off = aAtom[ma] + c * 128 + ((aLowr[ma] ^ c) << 4);
                asm volatile("ldmatrix.sync.aligned.m8n8.x4.shared.b16 {%0,%1,%2,%3}, [%4];"
                             : "=r"(afh[ma][0]), "=r"(afh[ma][1]), "=r"(afh[ma][2]), "=r"(afh[ma][3])
                             : "r"(aHi + off));
                asm volatile("ldmatrix.sync.aligned.m8n8.x4.shared.b16 {%0,%1,%2,%3}, [%4];"
                             : "=r"(afl[ma][0]), "=r"(afl[ma][1]), "=r"(afl[ma][2]), "=r"(afl[ma][3])
                             : "r"(aLo + off));
            }
#pragma unroll
            for (int na = 0; na < 4; na++) {
                int c = ka * 2 + bCbit;
                uint32_t off = bAtom[na] + c * 128 + ((bLowr[na] ^ c) << 4);
                asm volatile("ldmatrix.sync.aligned.m8n8.x2.shared.b16 {%0,%1}, [%2];"
                             : "=r"(bfh[na][0]), "=r"(bfh[na][1]) : "r"(bHi + off));
                asm volatile("ldmatrix.sync.aligned.m8n8.x2.shared.b16 {%0,%1}, [%2];"
                             : "=r"(bfl[na][0]), "=r"(bfl[na][1]) : "r"(bLo + off));
            }
#pragma unroll
            for (int ma = 0; ma < 2; ma++)
#pragma unroll
                for (int na = 0; na < 4; na++) {
                    MMA_BF16(acc[ma][na], afh[ma], bfh[na][0], bfh[na][1]);
                    MMA_BF16(acc[ma][na], afh[ma], bfl[na][0], bfl[na][1]);
                    MMA_BF16(acc[ma][na], afl[ma], bfh[na][0], bfh[na][1]);
                }
        }
    }

    float* Cout = C + (size_t)blockIdx.y * 64 * N;
    int g = lane >> 2, tig = lane & 3;
#pragma unroll
    for (int ma = 0; ma < 2; ma++)
#pragma unroll
        for (int na = 0; na < 4; na++) {
            int col = nBase + wn * 32 + na * 8 + tig * 2;
            int r0 = wm * 32 + ma * 16 + g;
            *reinterpret_cast<float2*>(Cout + (size_t)r0 * N + col) =
                make_float2(acc[ma][na][0], acc[ma][na][1]);
            *reinterpret_cast<float2*>(Cout + (size_t)(r0 + 8) * N + col) =
                make_float2(acc[ma][na][2], acc[ma][na][3]);
        }
}

// ================= fat output GEMM: 2-MMA (A split, W rn) + bias + fused lsm =================
__global__ __launch_bounds__(256) void k_outproj(const float* __restrict__ A,
                                                 const float* __restrict__ W,
                                                 const float* __restrict__ bias,
                                                 float* __restrict__ C,
                                                 float* __restrict__ pmax,
                                                 float* __restrict__ psum) {
    __shared__ __align__(16) uint32_t smAhi[2048], smAlo[2048];
    __shared__ __align__(16) uint32_t smB[4096];
    __shared__ float redMax[64][4];
    __shared__ float redSum[64][4];

    const int tid = threadIdx.x;
    const int lane = tid & 31, wid = tid >> 5;
    const int wm = wid & 1, wn = wid >> 1;
    const int nBase = blockIdx.x * 128;

    uint32_t aHi = (uint32_t)__cvta_generic_to_shared(smAhi);
    uint32_t aLo = (uint32_t)__cvta_generic_to_shared(smAlo);
    uint32_t bSm = (uint32_t)__cvta_generic_to_shared(smB);

    int aAtom[2], aLowr[2];
#pragma unroll
    for (int ma = 0; ma < 2; ma++) {
        int row = wm * 32 + ma * 16 + ((lane >> 3) & 1) * 8 + (lane & 7);
        aAtom[ma] = (row >> 3) << 10;
        aLowr[ma] = row & 7;
    }
    const int aCbit = lane >> 4;
    int bAtom[4], bLowr[4];
    const int ll = lane & 15;
#pragma unroll
    for (int na = 0; na < 4; na++) {
        int n = wn * 32 + na * 8 + (ll & 7);
        bAtom[na] = (n >> 3) << 10;
        bLowr[na] = n & 7;
    }
    const int bCbit = ll >> 3;

    float acc[2][4][4];
#pragma unroll
    for (int i = 0; i < 2; i++)
#pragma unroll
        for (int j = 0; j < 4; j++)
#pragma unroll
            for (int q = 0; q < 4; q++) acc[i][j][q] = 0.f;

    float4 ra[4], rb[8];
    const int arow = tid >> 4, ac4 = tid & 15;

    auto loadA = [&](int k0) {
#pragma unroll
        for (int s = 0; s < 4; s++)
            ra[s] = *reinterpret_cast<const float4*>(A + (size_t)(arow + 16 * s) * 1024 + k0 + ac4 * 4);
    };
    auto loadB = [&](int k0) {
#pragma unroll
        for (int s = 0; s < 8; s++) {
            int ng = nBase + arow + 16 * s;
            if (ng < VV)
                rb[s] = *reinterpret_cast<const float4*>(W + (size_t)ng * 1024 + k0 + ac4 * 4);
            else
                rb[s] = make_float4(0.f, 0.f, 0.f, 0.f);
        }
    };

    loadA(0);
    loadB(0);

    for (int kt = 0; kt < 16; kt++) {
        __syncthreads();
#pragma unroll
        for (int s = 0; s < 4; s++)
            split_store((char*)smAhi, (char*)smAlo, tile_off8(arow + 16 * s, ac4 * 4), ra[s]);
#pragma unroll
        for (int s = 0; s < 8; s++)
            rn_store((char*)smB, tile_off8(arow + 16 * s, ac4 * 4), rb[s]);
        __syncthreads();
        if (kt + 1 < 16) {
            loadA((kt + 1) * 64);
            loadB((kt + 1) * 64);
        }
#pragma unroll
        for (int ka = 0; ka < 4; ka++) {
            uint32_t afh[2][4], afl[2][4], bf[4][2];
#pragma unroll
            for (int ma = 0; ma < 2; ma++) {
                int c = ka * 2 + aCbit;
                uint32_t off = aAtom[ma] + c * 128 + ((aLowr[ma] ^ c) << 4);
                asm volatile("ldmatrix.sync.aligned.m8n8.x4.shared.b16 {%0,%1,%2,%3}, [%4];"
                             : "=r"(afh[ma][0]), "=r"(afh[ma][1]), "=r"(afh[ma][2]), "=r"(afh[ma][3])
                             : "r"(aHi + off));
                asm volatile("ldmatrix.sync.aligned.m8n8.x4.shared.b16 {%0,%1,%2,%3}, [%4];"
                             : "=r"(afl[ma][0]), "=r"(afl[ma][1]), "=r"(afl[ma][2]), "=r"(afl[ma][3])
                             : "r"(aLo + off));
            }
#pragma unroll
            for (int na = 0; na < 4; na++) {
                int c = ka * 2 + bCbit;
                uint32_t off = bAtom[na] + c * 128 + ((bLowr[na] ^ c) << 4);
                asm volatile("ldmatrix.sync.aligned.m8n8.x2.shared.b16 {%0,%1}, [%2];"
                             : "=r"(bf[na][0]), "=r"(bf[na][1]) : "r"(bSm + off));
            }
#pragma unroll
            for (int ma = 0; ma < 2; ma++)
#pragma unroll
                for (int na = 0; na < 4; na++) {
                    MMA_BF16(acc[ma][na], afh[ma], bf[na][0], bf[na][1]);
                    MMA_BF16(acc[ma][na], afl[ma], bf[na][0], bf[na][1]);
                }
        }
    }

    // epilogue: bias add, store C, per-row max/sumexp partials
    int g = lane >> 2, tig = lane & 3;
#pragma unroll
    for (int ma = 0; ma < 2; ma++)
#pragma unroll
        for (int na = 0; na < 4; na++) {
            int col = nBase + wn * 32 + na * 8 + tig * 2;
            int r0 = wm * 32 + ma * 16 + g;
            if (col < VV) {
                float b0 = bias[col];
                acc[ma][na][0] += b0; acc[ma][na][2] += b0;
                C[(size_t)r0 * VV + col]       = acc[ma][na][0];
                C[(size_t)(r0 + 8) * VV + col] = acc[ma][na][2];
            } else { acc[ma][na][0] = -1e30f; acc[ma][na][2] = -1e30f; }
            if (col + 1 < VV) {
                float b1 = bias[col + 1];
                acc[ma][na][1] += b1; acc[ma][na][3] += b1;
                C[(size_t)r0 * VV + col + 1]       = acc[ma][na][1];
                C[(size_t)(r0 + 8) * VV + col + 1] = acc[ma][na][3];
            } else { acc[ma][na][1] = -1e30f; acc[ma][na][3] = -1e30f; }
        }

#pragma unroll
    for (int ma = 0; ma < 2; ma++) {
        float m0 = -1e30f, m1 = -1e30f;
#pragma unroll
        for (int na = 0; na < 4; na++) {
            m0 = fmaxf(m0, fmaxf(acc[ma][na][0], acc[ma][na][1]));
            m1 = fmaxf(m1, fmaxf(acc[ma][na][2], acc[ma][na][3]));
        }
        m0 = fmaxf(m0, __shfl_xor_sync(~0u, m0, 1));
        m0 = fmaxf(m0, __shfl_xor_sync(~0u, m0, 2));
        m1 = fmaxf(m1, __shfl_xor_sync(~0u, m1, 1));
        m1 = fmaxf(m1, __shfl_xor_sync(~0u, m1, 2));
        if (tig == 0) {
            redMax[wm * 32 + ma * 16 + g][wn] = m0;
            redMax[wm * 32 + ma * 16 + g + 8][wn] = m1;
        }
    }
    __syncthreads();
#pragma unroll
    for (int ma = 0; ma < 2; ma++)
#pragma unroll
        for (int h = 0; h < 2; h++) {
            int row = wm * 32 + ma * 16 + g + h * 8;
            float rm = fmaxf(fmaxf(redMax[row][0], redMax[row][1]),
                             fmaxf(redMax[row][2], redMax[row][3]));
            float s = 0.f;
#pragma unroll
            for (int na = 0; na < 4; na++) {
                s += __expf(acc[ma][na][h * 2] - rm);
                s += __expf(acc[ma][na][h * 2 + 1] - rm);
            }
            s += __shfl_xor_sync(~0u, s, 1);
            s += __shfl_xor_sync(~0u, s, 2);
            if (tig == 0) redSum[row][wn] = s;
        }
    __syncthreads();
    if (tid < 64) {
        float rm = fmaxf(fmaxf(redMax[tid][0], redMax[tid][1]),
                         fmaxf(redMax[tid][2], redMax[tid][3]));
        float s = redSum[tid][0] + redSum[tid][1] + redSum[tid][2] + redSum[tid][3];
        pmax[tid * 512 + blockIdx.x] = rm;
        psum[tid * 512 + blockIdx.x] = s;
    }
}

// ---------------- attn logits reduce + softmax over L=512 ----------------
__global__ void k_attn_softmax(const float* __restrict__ part, const float* __restrict__ bias,
                               float* __restrict__ wout) {
    int b = blockIdx.x;
    int l = threadIdx.x;
    float v = bias[l];
#pragma unroll
    for (int s = 0; s < 16; s++) v += part[((size_t)s * BB + b) * LL + l];

    __shared__ float red[32];
    float m = v;
#pragma unroll
    for (int o = 16; o > 0; o >>= 1) m = fmaxf(m, __shfl_xor_sync(~0u, m, o));
    if ((threadIdx.x & 31) == 0) red[threadIdx.x >> 5] = m;
    __syncthreads();
    if (threadIdx.x < 32) {
        float t = (threadIdx.x < 16) ? red[threadIdx.x] : -1e30f;
#pragma unroll
        for (int o = 8; o > 0; o >>= 1) t = fmaxf(t, __shfl_xor_sync(~0u, t, o));
        if (threadIdx.x == 0) red[0] = t;
    }
    __syncthreads();
    float rowmax = red[0];
    __syncthreads();
    float e = expf(v - rowmax);
    float ssum = e;
#pragma unroll
    for (int o = 16; o > 0; o >>= 1) ssum += __shfl_xor_sync(~0u, ssum, o);
    if ((threadIdx.x & 31) == 0) red[threadIdx.x >> 5] = ssum;
    __syncthreads();
    if (threadIdx.x < 32) {
        float t = (threadIdx.x < 16) ? red[threadIdx.x] : 0.f;
#pragma unroll
        for (int o = 8; o > 0; o >>= 1) t += __shfl_xor_sync(~0u, t, o);
        if (threadIdx.x == 0) red[0] = t;
    }
    __syncthreads();
    wout[b * LL + l] = e / red[0];
}

// ---------------- attn context partials: 16 slices of 32 L-rows ----------------
__global__ void k_attnapp_part(const float* __restrict__ w, const float* __restrict__ enc,
                               float* __restrict__ part) {
    int s = blockIdx.x;
    int b = blockIdx.y;
    int d4 = threadIdx.x;
    __shared__ float ws[32];
    if (threadIdx.x < 32) ws[threadIdx.x] = w[b * LL + s * 32 + threadIdx.x];
    __syncthreads();
    const float4* ep = reinterpret_cast<const float4*>(enc + (size_t)b * LL * HH + (size_t)s * 32 * HH) + d4;
    float4 acc = make_float4(0.f, 0.f, 0.f, 0.f);
#pragma unroll 8
    for (int l = 0; l < 32; l++) {
        float4 v = ep[l * (HH / 4)];
        float c = ws[l];
        acc.x += c * v.x; acc.y += c * v.y; acc.z += c * v.z; acc.w += c * v.w;
    }
    reinterpret_cast<float4*>(part + ((size_t)s * BB + b) * HH)[d4] = acc;
}

// stage1: 4 groups x 4 splits -> partial; stage2: sum 4 groups
__global__ void k_attnred1(const float4* __restrict__ part, float4* __restrict__ mid) {
    int idx = blockIdx.x * 256 + threadIdx.x;   // 65536
    int grp = idx >> 14;
    int i = idx & 16383;
    float4 v = make_float4(0.f, 0.f, 0.f, 0.f);
#pragma unroll
    for (int s = 0; s < 4; s++) {
        float4 p = part[(size_t)(grp * 4 + s) * 16384 + i];
        v.x += p.x; v.y += p.y; v.z += p.z; v.w += p.w;
    }
    mid[idx] = v;
}
__global__ void k_attnred2(const float4* __restrict__ mid, float4* __restrict__ out) {
    int i = blockIdx.x * 256 + threadIdx.x;     // 16384
    float4 v = make_float4(0.f, 0.f, 0.f, 0.f);
#pragma unroll
    for (int g = 0; g < 4; g++) {
        float4 p = mid[(size_t)g * 16384 + i];
        v.x += p.x; v.y += p.y; v.z += p.z; v.w += p.w;
    }
    out[i] = v;
}

// ---------------- combine reduce + bias + relu (float4) ----------------
__global__ void k_combrelu(const float4* __restrict__ part, const float4* __restrict__ bias,
                           float4* __restrict__ out) {
    int idx = blockIdx.x * 256 + threadIdx.x;   // 16384
    float4 b = bias[idx & 255];
    float4 v = b;
#pragma unroll
    for (int s = 0; s < 16; s++) {
        float4 p = part[(size_t)s * 16384 + idx];
        v.x += p.x; v.y += p.y; v.z += p.z; v.w += p.w;
    }
    out[idx] = make_float4(fmaxf(v.x, 0.f), fmaxf(v.y, 0.f), fmaxf(v.z, 0.f), fmaxf(v.w, 0.f));
}

// ---------------- GRU gates (float4, split 4) ----------------
__global__ void k_gru(const float4* __restrict__ pgi, const float4* __restrict__ pgh,
                      const float4* __restrict__ bih, const float4* __restrict__ bhh,
                      const float4* __restrict__ hidden, float4* __restrict__ newh) {
    int idx = blockIdx.x * 256 + threadIdx.x;   // 16384
    int b = idx >> 8;
    int h4 = idx & 255;
    float4 ir = bih[h4], iz = bih[256 + h4], in_ = bih[512 + h4];
    float4 hr = bhh[h4], hz = bhh[256 + h4], hn = bhh[512 + h4];
#pragma unroll
    for (int s = 0; s < 4; s++) {
        size_t base = (size_t)(s * BB + b) * 768;
        float4 p;
        p = pgi[base + h4];        ir.x += p.x; ir.y += p.y; ir.z += p.z; ir.w += p.w;
        p = pgi[base + 256 + h4];  iz.x += p.x; iz.y += p.y; iz.z += p.z; iz.w += p.w;
        p = pgi[base + 512 + h4];  in_.x += p.x; in_.y += p.y; in_.z += p.z; in_.w += p.w;
        p = pgh[base + h4];        hr.x += p.x; hr.y += p.y; hr.z += p.z; hr.w += p.w;
        p = pgh[base + 256 + h4];  hz.x += p.x; hz.y += p.y; hz.z += p.z; hz.w += p.w;
        p = pgh[base + 512 + h4];  hn.x += p.x; hn.y += p.y; hn.z += p.z; hn.w += p.w;
    }
    float4 hd = hidden[idx];
    float4 o;
    {
        float r = 1.f / (1.f + expf(-(ir.x + hr.x)));
        float z = 1.f / (1.f + expf(-(iz.x + hz.x)));
        float n = tanhf(in_.x + r * hn.x);
        o.x = (1.f - z) * n + z * hd.x;
    }
    {
        float r = 1.f / (1.f + expf(-(ir.y + hr.y)));
        float z = 1.f / (1.f + expf(-(iz.y + hz.y)));
        float n = tanhf(in_.y + r * hn.y);
        o.y = (1.f - z) * n + z * hd.y;
    }
    {
        float r = 1.f / (1.f + expf(-(ir.z + hr.z)));
        float z = 1.f / (1.f + expf(-(iz.z + hz.z)));
        float n = tanhf(in_.z + r * hn.z);
        o.z = (1.f - z) * n + z * hd.z;
    }
    {
        float r = 1.f / (1.f + expf(-(ir.w + hr.w)));
        float z = 1.f / (1.f + expf(-(iz.w + hz.w)));
        float n = tanhf(in_.w + r * hn.w);
        o.w = (1.f - z) * n + z * hd.w;
    }
    newh[idx] = o;
}

// ---------------- lsm combine + write ----------------
__global__ void k_lsm_comb(const float* __restrict__ pmax, const float* __restrict__ psum,
                           float* __restrict__ lse) {
    int row = blockIdx.x;
    __shared__ float red[32];
    float m = -1e30f;
    for (int c = threadIdx.x; c < NBLK_OUT; c += 128) m = fmaxf(m, pmax[row * 512 + c]);
#pragma unroll
    for (int o = 16; o > 0; o >>= 1) m = fmaxf(m, __shfl_xor_sync(~0u, m, o));
    if ((threadIdx.x & 31) == 0) red[threadIdx.x >> 5] = m;
    __syncthreads();
    if (threadIdx.x < 32) {
        float t = (threadIdx.x < 4) ? red[threadIdx.x] : -1e30f;
#pragma unroll
        for (int o = 2; o > 0; o >>= 1) t = fmaxf(t, __shfl_xor_sync(~0u, t, o));
        if (threadIdx.x == 0) red[0] = t;
    }
    __syncthreads();
    float M = red[0];
    __syncthreads();
    float s = 0.f;
    for (int c = threadIdx.x; c < NBLK_OUT; c += 128)
        s += psum[row * 512 + c] * __expf(pmax[row * 512 + c] - M);
#pragma unroll
    for (int o = 16; o > 0; o >>= 1) s += __shfl_xor_sync(~0u, s, o);
    if ((threadIdx.x & 31) == 0) red[threadIdx.x >> 5] = s;
    __syncthreads();
    if (threadIdx.x < 32) {
        float t = (threadIdx.x < 4) ? red[threadIdx.x] : 0.f;
#pragma unroll
        for (int o = 2; o > 0; o >>= 1) t += __shfl_xor_sync(~0u, t, o);
        if (threadIdx.x == 0) lse[row] = M + logf(t);
    }
}

__global__ void k_lsm_write(float* __restrict__ out, const float* __restrict__ lse) {
    int c = blockIdx.x;          // 16 chunks
    int b = blockIdx.y;
    const int CH = (VV + 15) / 16;
    int start = c * CH;
    int end = min(start + CH, VV);
    float L = lse[b];
    float* row = out + (size_t)b * VV;
    for (int i = start + threadIdx.x; i < end; i += 256) row[i] -= L;
}

// ---------------- launch ----------------
extern "C" void kernel_launch(void* const* d_in, const int* in_sizes, int n_in,
                              void* d_out, int out_size) {
    const int*   ids    = (const int*)  d_in[0];
    const float* hidden = (const float*)d_in[1];
    const float* enc    = (const float*)d_in[2];
    const float* embW   = (const float*)d_in[3];
    const float* attnW  = (const float*)d_in[4];
    const float* attnb  = (const float*)d_in[5];
    const float* combW  = (const float*)d_in[6];
    const float* combb  = (const float*)d_in[7];
    const float* Wih    = (const float*)d_in[8];
    const float* Whh    = (const float*)d_in[9];
    const float* bih    = (const float*)d_in[10];
    const float* bhh    = (const float*)d_in[11];
    const float* outW   = (const float*)d_in[12];
    const float* outb   = (const float*)d_in[13];

    float* out  = (float*)d_out;
    float* newh = out + (size_t)BB * VV;

    float *p_attnw, *p_attnapp, *p_x, *p_pa, *p_pb, *p_pmax, *p_psum, *p_lse;
    cudaGetSymbolAddress((void**)&p_attnw, g_attnw);
    cudaGetSymbolAddress((void**)&p_attnapp, g_attnapp);
    cudaGetSymbolAddress((void**)&p_x, g_x);
    cudaGetSymbolAddress((void**)&p_pa, g_partA);
    cudaGetSymbolAddress((void**)&p_pb, g_partB);
    cudaGetSymbolAddress((void**)&p_pmax, g_pmax);
    cudaGetSymbolAddress((void**)&p_psum, g_psum);
    cudaGetSymbolAddress((void**)&p_lse, g_lse);

    // 1. attn logits: cat(gather(emb), hidden) @ attn_W^T, split-K 16
    gemm_bf16s<<<dim3(4, 16, 1), 256>>>(embW, hidden, ids, EE, EE + HH, attnW,
                                        p_pa, LL, 128, nullptr, nullptr, nullptr);

    // 2. reduce + bias + softmax over L
    k_attn_softmax<<<BB, 512>>>(p_pa, attnb, p_attnw);

    // 3. attention context (16 L-slices, two-stage float4 reduce; mid in g_partA)
    k_attnapp_part<<<dim3(16, BB), 256>>>(p_attnw, enc, p_pb);
    k_attnred1<<<256, 256>>>((const float4*)p_pb, (float4*)p_pa);
    k_attnred2<<<64, 256>>>((const float4*)p_pa, (float4*)p_attnapp);

    // 4. combine: cat(gather(emb), attn_applied) @ comb_W^T, split-K 16
    gemm_bf16s<<<dim3(8, 16, 1), 256>>>(embW, p_attnapp, ids, EE, EE + HH, combW,
                                        p_pa, EE, 128, nullptr, nullptr, nullptr);
    k_combrelu<<<64, 256>>>((const float4*)p_pa, (const float4*)combb, (float4*)p_x);

    // 5. GRU gi (z=0) and gh (z=1), split-K 4
    gemm_bf16s<<<dim3(24, 4, 2), 256>>>(p_x, nullptr, nullptr, HH, HH, Wih,
                                        p_pa, 3 * HH, 256,
                                        hidden, Whh, p_pb);
    k_gru<<<64, 256>>>((const float4*)p_pa, (const float4*)p_pb,
                       (const float4*)bih, (const float4*)bhh,
                       (const float4*)hidden, (float4*)newh);

    // 6. output projection (2-MMA split-A bf16) + fused lsm partials
    k_outproj<<<NBLK_OUT, 256>>>(newh, outW, outb, out, p_pmax, p_psum);

    // 7. lsm combine + write
    k_lsm_comb<<<BB, 128>>>(p_pmax, p_psum, p_lse);
    k_lsm_write<<<dim3(16, BB), 256>>>(out, p_lse);
}

// round 8
// speedup vs baseline: 1.1486x; 1.0600x over previous
#include <cuda_runtime.h>
#include <math.h>
#include <stdint.h>

#define BB 64
#define EE 1024
#define HH 1024
#define LL 512
#define VV 50257
#define NBLK_OUT 393   // ceil(VV/128)

// ---------------- scratch (device globals, no allocation) ----------------
__device__ float g_attnw[BB * LL];
__device__ float g_attnapp[BB * HH];
__device__ float g_x[BB * EE];
__device__ float g_partA[16 * BB * EE];      // attn 16*64*512, comb 16*64*1024, gi 4*64*3072
__device__ float g_partB[32 * BB * EE];      // attnapp 32*64*1024 = 2,097,152 floats; gh 4*64*3072 fits
__device__ float g_pmax[64 * 512];
__device__ float g_psum[64 * 512];
__device__ float g_lse[64];

// ---------------- helpers ----------------
__device__ __forceinline__ uint32_t pack_bf16(float lo, float hi) {
    uint32_t r;
    asm("cvt.rn.bf16x2.f32 %0, %1, %2;" : "=r"(r) : "f"(hi), "f"(lo));
    return r;
}
__device__ __forceinline__ int tile_off8(int row, int k) {
    int c = k >> 3;
    return (((row >> 3) << 3) + c) * 128 + (((row & 7) ^ c) << 4) + (k & 7) * 2;
}
__device__ __forceinline__ void split_store(char* hiP, char* loP, int off, float4 v) {
    uint32_t bx = __float_as_uint(v.x), by = __float_as_uint(v.y);
    uint32_t bz = __float_as_uint(v.z), bw = __float_as_uint(v.w);
    uint2 hi = make_uint2(__byte_perm(bx, by, 0x7632), __byte_perm(bz, bw, 0x7632));
    float lx = v.x - __uint_as_float(bx & 0xffff0000u);
    float ly = v.y - __uint_as_float(by & 0xffff0000u);
    float lz = v.z - __uint_as_float(bz & 0xffff0000u);
    float lw = v.w - __uint_as_float(bw & 0xffff0000u);
    uint2 lo = make_uint2(pack_bf16(lx, ly), pack_bf16(lz, lw));
    *reinterpret_cast<uint2*>(hiP + off) = hi;
    *reinterpret_cast<uint2*>(loP + off) = lo;
}
__device__ __forceinline__ void rn_store(char* P, int off, float4 v) {
    uint2 r = make_uint2(pack_bf16(v.x, v.y), pack_bf16(v.z, v.w));
    *reinterpret_cast<uint2*>(P + off) = r;
}

#define MMA_BF16(ac, a, b0, b1)                                                   \
    asm volatile("mma.sync.aligned.m16n8k16.row.col.f32.bf16.bf16.f32 "           \
                 "{%0,%1,%2,%3}, {%4,%5,%6,%7}, {%8,%9}, {%0,%1,%2,%3};"          \
                 : "+f"((ac)[0]), "+f"((ac)[1]), "+f"((ac)[2]), "+f"((ac)[3])     \
                 : "r"((a)[0]), "r"((a)[1]), "r"((a)[2]), "r"((a)[3]),            \
                   "r"(b0), "r"(b1))

// ================= split-bf16 tensor GEMM (split-K partials, 3-MMA) =================
__global__ __launch_bounds__(256) void gemm_bf16s(
    const float* __restrict__ A1, const float* __restrict__ A2,
    const int* __restrict__ gids, int K1, int K,
    const float* __restrict__ W, float* __restrict__ C, int N, int kChunk,
    const float* A1b, const float* Wb, float* Cb) {
    if (blockIdx.z == 1) { A1 = A1b; W = Wb; C = Cb; gids = nullptr; }

    __shared__ __align__(16) uint32_t smAhi[2048], smAlo[2048];
    __shared__ __align__(16) uint32_t smBhi[4096], smBlo[4096];

    const int tid = threadIdx.x;
    const int lane = tid & 31, wid = tid >> 5;
    const int wm = wid & 1, wn = wid >> 1;
    const int nBase = blockIdx.x * 128;
    const int kBase = blockIdx.y * kChunk;
    const int tiles = kChunk >> 6;

    uint32_t aHi = (uint32_t)__cvta_generic_to_shared(smAhi);
    uint32_t aLo = (uint32_t)__cvta_generic_to_shared(smAlo);
    uint32_t bHi = (uint32_t)__cvta_generic_to_shared(smBhi);
    uint32_t bLo = (uint32_t)__cvta_generic_to_shared(smBlo);

    int aAtom[2], aLowr[2];
#pragma unroll
    for (int ma = 0; ma < 2; ma++) {
        int row = wm * 32 + ma * 16 + ((lane >> 3) & 1) * 8 + (lane & 7);
        aAtom[ma] = (row >> 3) << 10;
        aLowr[ma] = row & 7;
    }
    const int aCbit = lane >> 4;
    int bAtom[4], bLowr[4];
    const int ll = lane & 15;
#pragma unroll
    for (int na = 0; na < 4; na++) {
        int n = wn * 32 + na * 8 + (ll & 7);
        bAtom[na] = (n >> 3) << 10;
        bLowr[na] = n & 7;
    }
    const int bCbit = ll >> 3;

    float acc[2][4][4];
#pragma unroll
    for (int i = 0; i < 2; i++)
#pragma unroll
        for (int j = 0; j < 4; j++)
#pragma unroll
            for (int q = 0; q < 4; q++) acc[i][j][q] = 0.f;

    float4 ra[4], rb[8];
    const int arow = tid >> 4, ac4 = tid & 15;

    auto loadA = [&](int k0) {
#pragma unroll
        for (int s = 0; s < 4; s++) {
            int row = arow + 16 * s;
            int k = k0 + ac4 * 4;
            const float* rp;
            if (k < K1) rp = (gids ? A1 + (size_t)gids[row] * K1 : A1 + (size_t)row * K1) + k;
            else        rp = A2 + (size_t)row * (K - K1) + (k - K1);
            ra[s] = *reinterpret_cast<const float4*>(rp);
        }
    };
    auto loadB = [&](int k0) {
#pragma unroll
        for (int s = 0; s < 8; s++)
            rb[s] = *reinterpret_cast<const float4*>(W + (size_t)(nBase + arow + 16 * s) * K + k0 + ac4 * 4);
    };

    loadA(kBase);
    loadB(kBase);

    for (int kt = 0; kt < tiles; kt++) {
        __syncthreads();
#pragma unroll
        for (int s = 0; s < 4; s++)
            split_store((char*)smAhi, (char*)smAlo, tile_off8(arow + 16 * s, ac4 * 4), ra[s]);
#pragma unroll
        for (int s = 0; s < 8; s++)
            split_store((char*)smBhi, (char*)smBlo, tile_off8(arow + 16 * s, ac4 * 4), rb[s]);
        __syncthreads();
        if (kt + 1 < tiles) {
            loadA(kBase + (kt + 1) * 64);
            loadB(kBase + (kt + 1) * 64);
        }
#pragma unroll
        for (int ka = 0; ka < 4; ka++) {
            uint32_t afh[2][4], afl[2][4], bfh[4][2], bfl[4][2];
#pragma unroll
            for (int ma = 0; ma < 2; ma++) {
                int c = ka * 2 + aCbit;
                uint32_t off = aAtom[ma] + c * 128 + ((aLowr[ma] ^ c) << 4);
                asm volatile("ldmatrix.sync.aligned.m8n8.x4.shared.b16 {%0,%1,%2,%3}, [%4];"
                             : "=r"(afh[ma][0]), "=r"(afh[ma][1]), "=r"(afh[ma][2]), "=r"(afh[ma][3])
                             : "r"(aHi + off));
                asm volatile("ldmatrix.sync.aligned.m8n8.x4.shared.b16 {%0,%1,%2,%3}, [%4];"
                             : "=r"(afl[ma][0]), "=r"(afl[ma][1]), "=r"(afl[ma][2]), "=r"(afl[ma][3])
                             : "r"(aLo + off));
            }
#pragma unroll
            for (int na = 0; na < 4; na++) {
                int c = ka * 2 + bCbit;
                uint32_t off = bAtom[na] + c * 128 + ((bLowr[na] ^ c) << 4);
                asm volatile("ldmatrix.sync.aligned.m8n8.x2.shared.b16 {%0,%1}, [%2];"
                             : "=r"(bfh[na][0]), "=r"(bfh[na][1]) : "r"(bHi + off));
                asm volatile("ldmatrix.sync.aligned.m8n8.x2.shared.b16 {%0,%1}, [%2];"
                             : "=r"(bfl[na][0]), "=r"(bfl[na][1]) : "r"(bLo + off));
            }
#pragma unroll
            for (int ma = 0; ma < 2; ma++)
#pragma unroll
                for (int na = 0; na < 4; na++) {
                    MMA_BF16(acc[ma][na], afh[ma], bfh[na][0], bfh[na][1]);
                    MMA_BF16(acc[ma][na], afh[ma], bfl[na][0], bfl[na][1]);
                    MMA_BF16(acc[ma][na], afl[ma], bfh[na][0], bfh[na][1]);
                }
        }
    }

    float* Cout = C + (size_t)blockIdx.y * 64 * N;
    int g = lane >> 2, tig = lane & 3;
#pragma unroll
    for (int ma = 0; ma < 2; ma++)
#pragma unroll
        for (int na = 0; na < 4; na++) {
            int col = nBase + wn * 32 + na * 8 + tig * 2;
            int r0 = wm * 32 + ma * 16 + g;
            *reinterpret_cast<float2*>(Cout + (size_t)r0 * N + col) =
                make_float2(acc[ma][na][0], acc[ma][na][1]);
            *reinterpret_cast<float2*>(Cout + (size_t)(r0 + 8) * N + col) =
                make_float2(acc[ma][na][2], acc[ma][na][3]);
        }
}

// ================= fat output GEMM: 2-MMA (A split, W rn) + bias + fused lsm =================
__global__ __launch_bounds__(256, 2) void k_outproj(const float* __restrict__ A,
                                                    const float* __restrict__ W,
                                                    const float* __restrict__ bias,
                                                    float* __restrict__ C,
                                                    float* __restrict__ pmax,
                                                    float* __restrict__ psum) {
    __shared__ __align__(16) uint32_t smAhi[2048], smAlo[2048];
    __shared__ __align__(16) uint32_t smB[4096];
    __shared__ float redMax[64][4];
    __shared__ float redSum[64][4];

    const int tid = threadIdx.x;
    const int lane = tid & 31, wid = tid >> 5;
    const int wm = wid & 1, wn = wid >> 1;
    const int nBase = blockIdx.x * 128;

    uint32_t aHi = (uint32_t)__cvta_generic_to_shared(smAhi);
    uint32_t aLo = (uint32_t)__cvta_generic_to_shared(smAlo);
    uint32_t bSm = (uint32_t)__cvta_generic_to_shared(smB);

    int aAtom[2], aLowr[2];
#pragma unroll
    for (int ma = 0; ma < 2; ma++) {
        int row = wm * 32 + ma * 16 + ((lane >> 3) & 1) * 8 + (lane & 7);
        aAtom[ma] = (row >> 3) << 10;
        aLowr[ma] = row & 7;
    }
    const int aCbit = lane >> 4;
    int bAtom[4], bLowr[4];
    const int ll = lane & 15;
#pragma unroll
    for (int na = 0; na < 4; na++) {
        int n = wn * 32 + na * 8 + (ll & 7);
        bAtom[na] = (n >> 3) << 10;
        bLowr[na] = n & 7;
    }
    const int bCbit = ll >> 3;

    float acc[2][4][4];
#pragma unroll
    for (int i = 0; i < 2; i++)
#pragma unroll
        for (int j = 0; j < 4; j++)
#pragma unroll
            for (int q = 0; q < 4; q++) acc[i][j][q] = 0.f;

    float4 ra[4], rb[8];
    const int arow = tid >> 4, ac4 = tid & 15;

    auto loadA = [&](int k0) {
#pragma unroll
        for (int s = 0; s < 4; s++)
            ra[s] = *reinterpret_cast<const float4*>(A + (size_t)(arow + 16 * s) * 1024 + k0 + ac4 * 4);
    };
    auto loadB = [&](int k0) {
#pragma unroll
        for (int s = 0; s < 8; s++) {
            int ng = nBase + arow + 16 * s;
            if (ng < VV)
                rb[s] = *reinterpret_cast<const float4*>(W + (size_t)ng * 1024 + k0 + ac4 * 4);
            else
                rb[s] = make_float4(0.f, 0.f, 0.f, 0.f);
        }
    };

    loadA(0);
    loadB(0);

    for (int kt = 0; kt < 16; kt++) {
        __syncthreads();
#pragma unroll
        for (int s = 0; s < 4; s++)
            split_store((char*)smAhi, (char*)smAlo, tile_off8(arow + 16 * s, ac4 * 4), ra[s]);
#pragma unroll
        for (int s = 0; s < 8; s++)
            rn_store((char*)smB, tile_off8(arow + 16 * s, ac4 * 4), rb[s]);
        __syncthreads();
        if (kt + 1 < 16) {
            loadA((kt + 1) * 64);
            loadB((kt + 1) * 64);
        }
#pragma unroll
        for (int ka = 0; ka < 4; ka++) {
            uint32_t afh[2][4], afl[2][4], bf[4][2];
#pragma unroll
            for (int ma = 0; ma < 2; ma++) {
                int c = ka * 2 + aCbit;
                uint32_t off = aAtom[ma] + c * 128 + ((aLowr[ma] ^ c) << 4);
                asm volatile("ldmatrix.sync.aligned.m8n8.x4.shared.b16 {%0,%1,%2,%3}, [%4];"
                             : "=r"(afh[ma][0]), "=r"(afh[ma][1]), "=r"(afh[ma][2]), "=r"(afh[ma][3])
                             : "r"(aHi + off));
                asm volatile("ldmatrix.sync.aligned.m8n8.x4.shared.b16 {%0,%1,%2,%3}, [%4];"
                             : "=r"(afl[ma][0]), "=r"(afl[ma][1]), "=r"(afl[ma][2]), "=r"(afl[ma][3])
                             : "r"(aLo + off));
            }
#pragma unroll
            for (int na = 0; na < 4; na++) {
                int c = ka * 2 + bCbit;
                uint32_t off = bAtom[na] + c * 128 + ((bLowr[na] ^ c) << 4);
                asm volatile("ldmatrix.sync.aligned.m8n8.x2.shared.b16 {%0,%1}, [%2];"
                             : "=r"(bf[na][0]), "=r"(bf[na][1]) : "r"(bSm + off));
            }
#pragma unroll
            for (int ma = 0; ma < 2; ma++)
#pragma unroll
                for (int na = 0; na < 4; na++) {
                    MMA_BF16(acc[ma][na], afh[ma], bf[na][0], bf[na][1]);
                    MMA_BF16(acc[ma][na], afl[ma], bf[na][0], bf[na][1]);
                }
        }
    }

    int g = lane >> 2, tig = lane & 3;
#pragma unroll
    for (int ma = 0; ma < 2; ma++)
#pragma unroll
        for (int na = 0; na < 4; na++) {
            int col = nBase + wn * 32 + na * 8 + tig * 2;
            int r0 = wm * 32 + ma * 16 + g;
            if (col < VV) {
                float b0 = bias[col];
                acc[ma][na][0] += b0; acc[ma][na][2] += b0;
                C[(size_t)r0 * VV + col]       = acc[ma][na][0];
                C[(size_t)(r0 + 8) * VV + col] = acc[ma][na][2];
            } else { acc[ma][na][0] = -1e30f; acc[ma][na][2] = -1e30f; }
            if (col + 1 < VV) {
                float b1 = bias[col + 1];
                acc[ma][na][1] += b1; acc[ma][na][3] += b1;
                C[(size_t)r0 * VV + col + 1]       = acc[ma][na][1];
                C[(size_t)(r0 + 8) * VV + col + 1] = acc[ma][na][3];
            } else { acc[ma][na][1] = -1e30f; acc[ma][na][3] = -1e30f; }
        }

#pragma unroll
    for (int ma = 0; ma < 2; ma++) {
        float m0 = -1e30f, m1 = -1e30f;
#pragma unroll
        for (int na = 0; na < 4; na++) {
            m0 = fmaxf(m0, fmaxf(acc[ma][na][0], acc[ma][na][1]));
            m1 = fmaxf(m1, fmaxf(acc[ma][na][2], acc[ma][na][3]));
        }
        m0 = fmaxf(m0, __shfl_xor_sync(~0u, m0, 1));
        m0 = fmaxf(m0, __shfl_xor_sync(~0u, m0, 2));
        m1 = fmaxf(m1, __shfl_xor_sync(~0u, m1, 1));
        m1 = fmaxf(m1, __shfl_xor_sync(~0u, m1, 2));
        if (tig == 0) {
            redMax[wm * 32 + ma * 16 + g][wn] = m0;
            redMax[wm * 32 + ma * 16 + g + 8][wn] = m1;
        }
    }
    __syncthreads();
#pragma unroll
    for (int ma = 0; ma < 2; ma++)
#pragma unroll
        for (int h = 0; h < 2; h++) {
            int row = wm * 32 + ma * 16 + g + h * 8;
            float rm = fmaxf(fmaxf(redMax[row][0], redMax[row][1]),
                             fmaxf(redMax[row][2], redMax[row][3]));
            float s = 0.f;
#pragma unroll
            for (int na = 0; na < 4; na++) {
                s += __expf(acc[ma][na][h * 2] - rm);
                s += __expf(acc[ma][na][h * 2 + 1] - rm);
            }
            s += __shfl_xor_sync(~0u, s, 1);
            s += __shfl_xor_sync(~0u, s, 2);
            if (tig == 0) redSum[row][wn] = s;
        }
    __syncthreads();
    if (tid < 64) {
        float rm = fmaxf(fmaxf(redMax[tid][0], redMax[tid][1]),
                         fmaxf(redMax[tid][2], redMax[tid][3]));
        float s = redSum[tid][0] + redSum[tid][1] + redSum[tid][2] + redSum[tid][3];
        pmax[tid * 512 + blockIdx.x] = rm;
        psum[tid * 512 + blockIdx.x] = s;
    }
}

// ---------------- attn logits reduce + softmax over L=512 ----------------
__global__ void k_attn_softmax(const float* __restrict__ part, const float* __restrict__ bias,
                               float* __restrict__ wout) {
    int b = blockIdx.x;
    int l = threadIdx.x;
    float v = bias[l];
#pragma unroll
    for (int s = 0; s < 16; s++) v += part[((size_t)s * BB + b) * LL + l];

    __shared__ float red[32];
    float m = v;
#pragma unroll
    for (int o = 16; o > 0; o >>= 1) m = fmaxf(m, __shfl_xor_sync(~0u, m, o));
    if ((threadIdx.x & 31) == 0) red[threadIdx.x >> 5] = m;
    __syncthreads();
    if (threadIdx.x < 32) {
        float t = (threadIdx.x < 16) ? red[threadIdx.x] : -1e30f;
#pragma unroll
        for (int o = 8; o > 0; o >>= 1) t = fmaxf(t, __shfl_xor_sync(~0u, t, o));
        if (threadIdx.x == 0) red[0] = t;
    }
    __syncthreads();
    float rowmax = red[0];
    __syncthreads();
    float e = expf(v - rowmax);
    float ssum = e;
#pragma unroll
    for (int o = 16; o > 0; o >>= 1) ssum += __shfl_xor_sync(~0u, ssum, o);
    if ((threadIdx.x & 31) == 0) red[threadIdx.x >> 5] = ssum;
    __syncthreads();
    if (threadIdx.x < 32) {
        float t = (threadIdx.x < 16) ? red[threadIdx.x] : 0.f;
#pragma unroll
        for (int o = 8; o > 0; o >>= 1) t += __shfl_xor_sync(~0u, t, o);
        if (threadIdx.x == 0) red[0] = t;
    }
    __syncthreads();
    wout[b * LL + l] = e / red[0];
}

// ---------------- attn context partials: 32 slices of 16 L-rows ----------------
__global__ void k_attnapp_part(const float* __restrict__ w, const float* __restrict__ enc,
                               float* __restrict__ part) {
    int s = blockIdx.x;      // 32 slices
    int b = blockIdx.y;
    int d4 = threadIdx.x;
    __shared__ float ws[16];
    if (threadIdx.x < 16) ws[threadIdx.x] = w[b * LL + s * 16 + threadIdx.x];
    __syncthreads();
    const float4* ep = reinterpret_cast<const float4*>(enc + (size_t)b * LL * HH + (size_t)s * 16 * HH) + d4;
    float4 acc = make_float4(0.f, 0.f, 0.f, 0.f);
#pragma unroll
    for (int l = 0; l < 16; l++) {
        float4 v = ep[l * (HH / 4)];
        float c = ws[l];
        acc.x += c * v.x; acc.y += c * v.y; acc.z += c * v.z; acc.w += c * v.w;
    }
    reinterpret_cast<float4*>(part + ((size_t)s * BB + b) * HH)[d4] = acc;
}

__global__ void k_attnred(const float4* __restrict__ part, float4* __restrict__ out) {
    int i = blockIdx.x * 128 + threadIdx.x;     // 16384 float4 outputs
    float4 v = make_float4(0.f, 0.f, 0.f, 0.f);
#pragma unroll
    for (int s = 0; s < 32; s++) {
        float4 p = part[(size_t)s * 16384 + i];
        v.x += p.x; v.y += p.y; v.z += p.z; v.w += p.w;
    }
    out[i] = v;
}

// ---------------- combine reduce + bias + relu (float4) ----------------
__global__ void k_combrelu(const float4* __restrict__ part, const float4* __restrict__ bias,
                           float4* __restrict__ out) {
    int idx = blockIdx.x * 256 + threadIdx.x;   // 16384
    float4 b = bias[idx & 255];
    float4 v = b;
#pragma unroll
    for (int s = 0; s < 16; s++) {
        float4 p = part[(size_t)s * 16384 + idx];
        v.x += p.x; v.y += p.y; v.z += p.z; v.w += p.w;
    }
    out[idx] = make_float4(fmaxf(v.x, 0.f), fmaxf(v.y, 0.f), fmaxf(v.z, 0.f), fmaxf(v.w, 0.f));
}

// ---------------- GRU gates (float4, split 4) ----------------
__global__ void k_gru(const float4* __restrict__ pgi, const float4* __restrict__ pgh,
                      const float4* __restrict__ bih, const float4* __restrict__ bhh,
                      const float4* __restrict__ hidden, float4* __restrict__ newh) {
    int idx = blockIdx.x * 256 + threadIdx.x;   // 16384
    int b = idx >> 8;
    int h4 = idx & 255;
    float4 ir = bih[h4], iz = bih[256 + h4], in_ = bih[512 + h4];
    float4 hr = bhh[h4], hz = bhh[256 + h4], hn = bhh[512 + h4];
#pragma unroll
    for (int s = 0; s < 4; s++) {
        size_t base = (size_t)(s * BB + b) * 768;
        float4 p;
        p = pgi[base + h4];        ir.x += p.x; ir.y += p.y; ir.z += p.z; ir.w += p.w;
        p = pgi[base + 256 + h4];  iz.x += p.x; iz.y += p.y; iz.z += p.z; iz.w += p.w;
        p = pgi[base + 512 + h4];  in_.x += p.x; in_.y += p.y; in_.z += p.z; in_.w += p.w;
        p = pgh[base + h4];        hr.x += p.x; hr.y += p.y; hr.z += p.z; hr.w += p.w;
        p = pgh[base + 256 + h4];  hz.x += p.x; hz.y += p.y; hz.z += p.z; hz.w += p.w;
        p = pgh[base + 512 + h4];  hn.x += p.x; hn.y += p.y; hn.z += p.z; hn.w += p.w;
    }
    float4 hd = hidden[idx];
    float4 o;
    {
        float r = 1.f / (1.f + expf(-(ir.x + hr.x)));
        float z = 1.f / (1.f + expf(-(iz.x + hz.x)));
        float n = tanhf(in_.x + r * hn.x);
        o.x = (1.f - z) * n + z * hd.x;
    }
    {
        float r = 1.f / (1.f + expf(-(ir.y + hr.y)));
        float z = 1.f / (1.f + expf(-(iz.y + hz.y)));
        float n = tanhf(in_.y + r * hn.y);
        o.y = (1.f - z) * n + z * hd.y;
    }
    {
        float r = 1.f / (1.f + expf(-(ir.z + hr.z)));
        float z = 1.f / (1.f + expf(-(iz.z + hz.z)));
        float n = tanhf(in_.z + r * hn.z);
        o.z = (1.f - z) * n + z * hd.z;
    }
    {
        float r = 1.f / (1.f + expf(-(ir.w + hr.w)));
        float z = 1.f / (1.f + expf(-(iz.w + hz.w)));
        float n = tanhf(in_.w + r * hn.w);
        o.w = (1.f - z) * n + z * hd.w;
    }
    newh[idx] = o;
}

// ---------------- lsm combine + write ----------------
__global__ void k_lsm_comb(const float* __restrict__ pmax, const float* __restrict__ psum,
                           float* __restrict__ lse) {
    int row = blockIdx.x;
    __shared__ float red[32];
    float m = -1e30f;
    for (int c = threadIdx.x; c < NBLK_OUT; c += 128) m = fmaxf(m, pmax[row * 512 + c]);
#pragma unroll
    for (int o = 16; o > 0; o >>= 1) m = fmaxf(m, __shfl_xor_sync(~0u, m, o));
    if ((threadIdx.x & 31) == 0) red[threadIdx.x >> 5] = m;
    __syncthreads();
    if (threadIdx.x < 32) {
        float t = (threadIdx.x < 4) ? red[threadIdx.x] : -1e30f;
#pragma unroll
        for (int o = 2; o > 0; o >>= 1) t = fmaxf(t, __shfl_xor_sync(~0u, t, o));
        if (threadIdx.x == 0) red[0] = t;
    }
    __syncthreads();
    float M = red[0];
    __syncthreads();
    float s = 0.f;
    for (int c = threadIdx.x; c < NBLK_OUT; c += 128)
        s += psum[row * 512 + c] * __expf(pmax[row * 512 + c] - M);
#pragma unroll
    for (int o = 16; o > 0; o >>= 1) s += __shfl_xor_sync(~0u, s, o);
    if ((threadIdx.x & 31) == 0) red[threadIdx.x >> 5] = s;
    __syncthreads();
    if (threadIdx.x < 32) {
        float t = (threadIdx.x < 4) ? red[threadIdx.x] : 0.f;
#pragma unroll
        for (int o = 2; o > 0; o >>= 1) t += __shfl_xor_sync(~0u, t, o);
        if (threadIdx.x == 0) lse[row] = M + logf(t);
    }
}

// flat float4 over the whole [64*VV] region (base is aligned, 64*VV % 4 == 0).
// float4s that straddle a row boundary are handled element-wise.
__global__ void k_lsm_write(float* __restrict__ out, const float* __restrict__ lse) {
    const int TOT4 = (BB * VV) >> 2;            // 804112
    int i4 = blockIdx.x * 256 + threadIdx.x;
    if (i4 >= TOT4) return;
    int e0 = i4 * 4;
    int b0 = e0 / VV;
    int b3 = (e0 + 3) / VV;
    float4* p = reinterpret_cast<float4*>(out) + i4;
    float4 v = *p;
    if (b0 == b3) {
        float L = lse[b0];
        v.x -= L; v.y -= L; v.z -= L; v.w -= L;
    } else {
        v.x -= lse[e0 / VV];
        v.y -= lse[(e0 + 1) / VV];
        v.z -= lse[(e0 + 2) / VV];
        v.w -= lse[(e0 + 3) / VV];
    }
    *p = v;
}

// ---------------- launch ----------------
extern "C" void kernel_launch(void* const* d_in, const int* in_sizes, int n_in,
                              void* d_out, int out_size) {
    const int*   ids    = (const int*)  d_in[0];
    const float* hidden = (const float*)d_in[1];
    const float* enc    = (const float*)d_in[2];
    const float* embW   = (const float*)d_in[3];
    const float* attnW  = (const float*)d_in[4];
    const float* attnb  = (const float*)d_in[5];
    const float* combW  = (const float*)d_in[6];
    const float* combb  = (const float*)d_in[7];
    const float* Wih    = (const float*)d_in[8];
    const float* Whh    = (const float*)d_in[9];
    const float* bih    = (const float*)d_in[10];
    const float* bhh    = (const float*)d_in[11];
    const float* outW   = (const float*)d_in[12];
    const float* outb   = (const float*)d_in[13];

    float* out  = (float*)d_out;
    float* newh = out + (size_t)BB * VV;

    float *p_attnw, *p_attnapp, *p_x, *p_pa, *p_pb, *p_pmax, *p_psum, *p_lse;
    cudaGetSymbolAddress((void**)&p_attnw, g_attnw);
    cudaGetSymbolAddress((void**)&p_attnapp, g_attnapp);
    cudaGetSymbolAddress((void**)&p_x, g_x);
    cudaGetSymbolAddress((void**)&p_pa, g_partA);
    cudaGetSymbolAddress((void**)&p_pb, g_partB);
    cudaGetSymbolAddress((void**)&p_pmax, g_pmax);
    cudaGetSymbolAddress((void**)&p_psum, g_psum);
    cudaGetSymbolAddress((void**)&p_lse, g_lse);

    // 1. attn logits: cat(gather(emb), hidden) @ attn_W^T, split-K 16
    gemm_bf16s<<<dim3(4, 16, 1), 256>>>(embW, hidden, ids, EE, EE + HH, attnW,
                                        p_pa, LL, 128, nullptr, nullptr, nullptr);

    // 2. reduce + bias + softmax over L
    k_attn_softmax<<<BB, 512>>>(p_pa, attnb, p_attnw);

    // 3. attention context (32 L-slices + single reduce)
    k_attnapp_part<<<dim3(32, BB), 256>>>(p_attnw, enc, p_pb);
    k_attnred<<<128, 128>>>((const float4*)p_pb, (float4*)p_attnapp);

    // 4. combine: cat(gather(emb), attn_applied) @ comb_W^T, split-K 16
    gemm_bf16s<<<dim3(8, 16, 1), 256>>>(embW, p_attnapp, ids, EE, EE + HH, combW,
                                        p_pa, EE, 128, nullptr, nullptr, nullptr);
    k_combrelu<<<64, 256>>>((const float4*)p_pa, (const float4*)combb, (float4*)p_x);

    // 5. GRU gi (z=0) and gh (z=1), split-K 4
    gemm_bf16s<<<dim3(24, 4, 2), 256>>>(p_x, nullptr, nullptr, HH, HH, Wih,
                                        p_pa, 3 * HH, 256,
                                        hidden, Whh, p_pb);
    k_gru<<<64, 256>>>((const float4*)p_pa, (const float4*)p_pb,
                       (const float4*)bih, (const float4*)bhh,
                       (const float4*)hidden, (float4*)newh);

    // 6. output projection (2-MMA split-A bf16, 2 blocks/SM) + fused lsm partials
    k_outproj<<<NBLK_OUT, 256>>>(newh, outW, outb, out, p_pmax, p_psum);

    // 7. lsm combine + write
    k_lsm_comb<<<BB, 128>>>(p_pmax, p_psum, p_lse);
    k_lsm_write<<<(BB * VV / 4 + 255) / 256, 256>>>(out, p_lse);
}

// round 9
// speedup vs baseline: 1.2383x; 1.0780x over previous
#include <cuda_runtime.h>
#include <math.h>
#include <stdint.h>

#define BB 64
#define EE 1024
#define HH 1024
#define LL 512
#define VV 50257
#define NBLK_OUT 393   // ceil(VV/128)

// ---------------- scratch (device globals, no allocation) ----------------
__device__ float g_attnw[BB * LL];
__device__ float g_attnapp[BB * HH];
__device__ float g_x[BB * EE];
__device__ float g_partA[16 * BB * EE];      // attn 16*64*512, comb 16*64*1024, gi 4*64*3072
__device__ float g_partB[32 * BB * EE];      // attnapp 32*64*1024 = 2,097,152 floats; gh 4*64*3072 fits
__device__ float g_pmax[64 * 512];
__device__ float g_psum[64 * 512];
__device__ float g_lse[64];

// ---------------- helpers ----------------
__device__ __forceinline__ uint32_t pack_bf16(float lo, float hi) {
    uint32_t r;
    asm("cvt.rn.bf16x2.f32 %0, %1, %2;" : "=r"(r) : "f"(hi), "f"(lo));
    return r;
}
__device__ __forceinline__ int tile_off8(int row, int k) {
    int c = k >> 3;
    return (((row >> 3) << 3) + c) * 128 + (((row & 7) ^ c) << 4) + (k & 7) * 2;
}
__device__ __forceinline__ void split_store(char* hiP, char* loP, int off, float4 v) {
    uint32_t bx = __float_as_uint(v.x), by = __float_as_uint(v.y);
    uint32_t bz = __float_as_uint(v.z), bw = __float_as_uint(v.w);
    uint2 hi = make_uint2(__byte_perm(bx, by, 0x7632), __byte_perm(bz, bw, 0x7632));
    float lx = v.x - __uint_as_float(bx & 0xffff0000u);
    float ly = v.y - __uint_as_float(by & 0xffff0000u);
    float lz = v.z - __uint_as_float(bz & 0xffff0000u);
    float lw = v.w - __uint_as_float(bw & 0xffff0000u);
    uint2 lo = make_uint2(pack_bf16(lx, ly), pack_bf16(lz, lw));
    *reinterpret_cast<uint2*>(hiP + off) = hi;
    *reinterpret_cast<uint2*>(loP + off) = lo;
}
__device__ __forceinline__ void rn_store(char* P, int off, float4 v) {
    uint2 r = make_uint2(pack_bf16(v.x, v.y), pack_bf16(v.z, v.w));
    *reinterpret_cast<uint2*>(P + off) = r;
}

#define MMA_BF16(ac, a, b0, b1)                                                   \
    asm volatile("mma.sync.aligned.m16n8k16.row.col.f32.bf16.bf16.f32 "           \
                 "{%0,%1,%2,%3}, {%4,%5,%6,%7}, {%8,%9}, {%0,%1,%2,%3};"          \
                 : "+f"((ac)[0]), "+f"((ac)[1]), "+f"((ac)[2]), "+f"((ac)[3])     \
                 : "r"((a)[0]), "r"((a)[1]), "r"((a)[2]), "r"((a)[3]),            \
                   "r"(b0), "r"(b1))

// ================= split-bf16 tensor GEMM (split-K partials, 3-MMA) =================
__global__ __launch_bounds__(256) void gemm_bf16s(
    const float* __restrict__ A1, const float* __restrict__ A2,
    const int* __restrict__ gids, int K1, int K,
    const float* __restrict__ W, float* __restrict__ C, int N, int kChunk,
    const float* A1b, const float* Wb, float* Cb) {
    if (blockIdx.z == 1) { A1 = A1b; W = Wb; C = Cb; gids = nullptr; }

    __shared__ __align__(16) uint32_t smAhi[2048], smAlo[2048];
    __shared__ __align__(16) uint32_t smBhi[4096], smBlo[4096];

    const int tid = threadIdx.x;
    const int lane = tid & 31, wid = tid >> 5;
    const int wm = wid & 1, wn = wid >> 1;
    const int nBase = blockIdx.x * 128;
    const int kBase = blockIdx.y * kChunk;
    const int tiles = kChunk >> 6;

    uint32_t aHi = (uint32_t)__cvta_generic_to_shared(smAhi);
    uint32_t aLo = (uint32_t)__cvta_generic_to_shared(smAlo);
    uint32_t bHi = (uint32_t)__cvta_generic_to_shared(smBhi);
    uint32_t bLo = (uint32_t)__cvta_generic_to_shared(smBlo);

    int aAtom[2], aLowr[2];
#pragma unroll
    for (int ma = 0; ma < 2; ma++) {
        int row = wm * 32 + ma * 16 + ((lane >> 3) & 1) * 8 + (lane & 7);
        aAtom[ma] = (row >> 3) << 10;
        aLowr[ma] = row & 7;
    }
    const int aCbit = lane >> 4;
    int bAtom[4], bLowr[4];
    const int ll = lane & 15;
#pragma unroll
    for (int na = 0; na < 4; na++) {
        int n = wn * 32 + na * 8 + (ll & 7);
        bAtom[na] = (n >> 3) << 10;
        bLowr[na] = n & 7;
    }
    const int bCbit = ll >> 3;

    float acc[2][4][4];
#pragma unroll
    for (int i = 0; i < 2; i++)
#pragma unroll
        for (int j = 0; j < 4; j++)
#pragma unroll
            for (int q = 0; q < 4; q++) acc[i][j][q] = 0.f;

    float4 ra[4], rb[8];
    const int arow = tid >> 4, ac4 = tid & 15;

    auto loadA = [&](int k0) {
#pragma unroll
        for (int s = 0; s < 4; s++) {
            int row = arow + 16 * s;
            int k = k0 + ac4 * 4;
            const float* rp;
            if (k < K1) rp = (gids ? A1 + (size_t)gids[row] * K1 : A1 + (size_t)row * K1) + k;
            else        rp = A2 + (size_t)row * (K - K1) + (k - K1);
            ra[s] = *reinterpret_cast<const float4*>(rp);
        }
    };
    auto loadB = [&](int k0) {
#pragma unroll
        for (int s = 0; s < 8; s++)
            rb[s] = __ldcs(reinterpret_cast<const float4*>(
                W + (size_t)(nBase + arow + 16 * s) * K + k0 + ac4 * 4));
    };

    loadA(kBase);
    loadB(kBase);

    for (int kt = 0; kt < tiles; kt++) {
        __syncthreads();
#pragma unroll
        for (int s = 0; s < 4; s++)
            split_store((char*)smAhi, (char*)smAlo, tile_off8(arow + 16 * s, ac4 * 4), ra[s]);
#pragma unroll
        for (int s = 0; s < 8; s++)
            split_store((char*)smBhi, (char*)smBlo, tile_off8(arow + 16 * s, ac4 * 4), rb[s]);
        __syncthreads();
        if (kt + 1 < tiles) {
            loadA(kBase + (kt + 1) * 64);
            loadB(kBase + (kt + 1) * 64);
        }
#pragma unroll
        for (int ka = 0; ka < 4; ka++) {
            uint32_t afh[2][4], afl[2][4], bfh[4][2], bfl[4][2];
#pragma unroll
            for (int ma = 0; ma < 2; ma++) {
                int c = ka * 2 + aCbit;
                uint32_t off = aAtom[ma] + c * 128 + ((aLowr[ma] ^ c) << 4);
                asm volatile("ldmatrix.sync.aligned.m8n8.x4.shared.b16 {%0,%1,%2,%3}, [%4];"
                             : "=r"(afh[ma][0]), "=r"(afh[ma][1]), "=r"(afh[ma][2]), "=r"(afh[ma][3])
                             : "r"(aHi + off));
                asm volatile("ldmatrix.sync.aligned.m8n8.x4.shared.b16 {%0,%1,%2,%3}, [%4];"
                             : "=r"(afl[ma][0]), "=r"(afl[ma][1]), "=r"(afl[ma][2]), "=r"(afl[ma][3])
                             : "r"(aLo + off));
            }
#pragma unroll
            for (int na = 0; na < 4; na++) {
                int c = ka * 2 + bCbit;
                uint32_t off = bAtom[na] + c * 128 + ((bLowr[na] ^ c) << 4);
                asm volatile("ldmatrix.sync.aligned.m8n8.x2.shared.b16 {%0,%1}, [%2];"
                             : "=r"(bfh[na][0]), "=r"(bfh[na][1]) : "r"(bHi + off));
                asm volatile("ldmatrix.sync.aligned.m8n8.x2.shared.b16 {%0,%1}, [%2];"
                             : "=r"(bfl[na][0]), "=r"(bfl[na][1]) : "r"(bLo + off));
            }
#pragma unroll
            for (int ma = 0; ma < 2; ma++)
#pragma unroll
                for (int na = 0; na < 4; na++) {
                    MMA_BF16(acc[ma][na], afh[ma], bfh[na][0], bfh[na][1]);
                    MMA_BF16(acc[ma][na], afh[ma], bfl[na][0], bfl[na][1]);
                    MMA_BF16(acc[ma][na], afl[ma], bfh[na][0], bfh[na][1]);
                }
        }
    }

    float* Cout = C + (size_t)blockIdx.y * 64 * N;
    int g = lane >> 2, tig = lane & 3;
#pragma unroll
    for (int ma = 0; ma < 2; ma++)
#pragma unroll
        for (int na = 0; na < 4; na++) {
            int col = nBase + wn * 32 + na * 8 + tig * 2;
            int r0 = wm * 32 + ma * 16 + g;
            *reinterpret_cast<float2*>(Cout + (size_t)r0 * N + col) =
                make_float2(acc[ma][na][0], acc[ma][na][1]);
            *reinterpret_cast<float2*>(Cout + (size_t)(r0 + 8) * N + col) =
                make_float2(acc[ma][na][2], acc[ma][na][3]);
        }
}

// ================= fat output GEMM: 2-MMA (A split, W rn) + bias + fused lsm =================
__global__ __launch_bounds__(256, 2) void k_outproj(const float* __restrict__ A,
                                                    const float* __restrict__ W,
                                                    const float* __restrict__ bias,
                                                    float* __restrict__ C,
                                                    float* __restrict__ pmax,
                                                    float* __restrict__ psum) {
    __shared__ __align__(16) uint32_t smAhi[2048], smAlo[2048];
    __shared__ __align__(16) uint32_t smB[4096];
    __shared__ float redMax[64][4];
    __shared__ float redSum[64][4];

    const int tid = threadIdx.x;
    const int lane = tid & 31, wid = tid >> 5;
    const int wm = wid & 1, wn = wid >> 1;
    const int nBase = blockIdx.x * 128;

    uint32_t aHi = (uint32_t)__cvta_generic_to_shared(smAhi);
    uint32_t aLo = (uint32_t)__cvta_generic_to_shared(smAlo);
    uint32_t bSm = (uint32_t)__cvta_generic_to_shared(smB);

    int aAtom[2], aLowr[2];
#pragma unroll
    for (int ma = 0; ma < 2; ma++) {
        int row = wm * 32 + ma * 16 + ((lane >> 3) & 1) * 8 + (lane & 7);
        aAtom[ma] = (row >> 3) << 10;
        aLowr[ma] = row & 7;
    }
    const int aCbit = lane >> 4;
    int bAtom[4], bLowr[4];
    const int ll = lane & 15;
#pragma unroll
    for (int na = 0; na < 4; na++) {
        int n = wn * 32 + na * 8 + (ll & 7);
        bAtom[na] = (n >> 3) << 10;
        bLowr[na] = n & 7;
    }
    const int bCbit = ll >> 3;

    float acc[2][4][4];
#pragma unroll
    for (int i = 0; i < 2; i++)
#pragma unroll
        for (int j = 0; j < 4; j++)
#pragma unroll
            for (int q = 0; q < 4; q++) acc[i][j][q] = 0.f;

    float4 ra[4], rb[8];
    const int arow = tid >> 4, ac4 = tid & 15;

    auto loadA = [&](int k0) {
#pragma unroll
        for (int s = 0; s < 4; s++)
            ra[s] = *reinterpret_cast<const float4*>(A + (size_t)(arow + 16 * s) * 1024 + k0 + ac4 * 4);
    };
    auto loadB = [&](int k0) {
#pragma unroll
        for (int s = 0; s < 8; s++) {
            int ng = nBase + arow + 16 * s;
            if (ng < VV)
                rb[s] = __ldcs(reinterpret_cast<const float4*>(W + (size_t)ng * 1024 + k0 + ac4 * 4));
            else
                rb[s] = make_float4(0.f, 0.f, 0.f, 0.f);
        }
    };

    loadA(0);
    loadB(0);

    for (int kt = 0; kt < 16; kt++) {
        __syncthreads();
#pragma unroll
        for (int s = 0; s < 4; s++)
            split_store((char*)smAhi, (char*)smAlo, tile_off8(arow + 16 * s, ac4 * 4), ra[s]);
#pragma unroll
        for (int s = 0; s < 8; s++)
            rn_store((char*)smB, tile_off8(arow + 16 * s, ac4 * 4), rb[s]);
        __syncthreads();
        if (kt + 1 < 16) {
            loadA((kt + 1) * 64);
            loadB((kt + 1) * 64);
        }
#pragma unroll
        for (int ka = 0; ka < 4; ka++) {
            uint32_t afh[2][4], afl[2][4], bf[4][2];
#pragma unroll
            for (int ma = 0; ma < 2; ma++) {
                int c = ka * 2 + aCbit;
                uint32_t off = aAtom[ma] + c * 128 + ((aLowr[ma] ^ c) << 4);
                asm volatile("ldmatrix.sync.aligned.m8n8.x4.shared.b16 {%0,%1,%2,%3}, [%4];"
                             : "=r"(afh[ma][0]), "=r"(afh[ma][1]), "=r"(afh[ma][2]), "=r"(afh[ma][3])
                             : "r"(aHi + off));
                asm volatile("ldmatrix.sync.aligned.m8n8.x4.shared.b16 {%0,%1,%2,%3}, [%4];"
                             : "=r"(afl[ma][0]), "=r"(afl[ma][1]), "=r"(afl[ma][2]), "=r"(afl[ma][3])
                             : "r"(aLo + off));
            }
#pragma unroll
            for (int na = 0; na < 4; na++) {
                int c = ka * 2 + bCbit;
                uint32_t off = bAtom[na] + c * 128 + ((bLowr[na] ^ c) << 4);
                asm volatile("ldmatrix.sync.aligned.m8n8.x2.shared.b16 {%0,%1}, [%2];"
                             : "=r"(bf[na][0]), "=r"(bf[na][1]) : "r"(bSm + off));
            }
#pragma unroll
            for (int ma = 0; ma < 2; ma++)
#pragma unroll
                for (int na = 0; na < 4; na++) {
                    MMA_BF16(acc[ma][na], afh[ma], bf[na][0], bf[na][1]);
                    MMA_BF16(acc[ma][na], afl[ma], bf[na][0], bf[na][1]);
                }
        }
    }

    int g = lane >> 2, tig = lane & 3;
#pragma unroll
    for (int ma = 0; ma < 2; ma++)
#pragma unroll
        for (int na = 0; na < 4; na++) {
            int col = nBase + wn * 32 + na * 8 + tig * 2;
            int r0 = wm * 32 + ma * 16 + g;
            if (col < VV) {
                float b0 = bias[col];
                acc[ma][na][0] += b0; acc[ma][na][2] += b0;
                C[(size_t)r0 * VV + col]       = acc[ma][na][0];
                C[(size_t)(r0 + 8) * VV + col] = acc[ma][na][2];
            } else { acc[ma][na][0] = -1e30f; acc[ma][na][2] = -1e30f; }
            if (col + 1 < VV) {
                float b1 = bias[col + 1];
                acc[ma][na][1] += b1; acc[ma][na][3] += b1;
                C[(size_t)r0 * VV + col + 1]       = acc[ma][na][1];
                C[(size_t)(r0 + 8) * VV + col + 1] = acc[ma][na][3];
            } else { acc[ma][na][1] = -1e30f; acc[ma][na][3] = -1e30f; }
        }

#pragma unroll
    for (int ma = 0; ma < 2; ma++) {
        float m0 = -1e30f, m1 = -1e30f;
#pragma unroll
        for (int na = 0; na < 4; na++) {
            m0 = fmaxf(m0, fmaxf(acc[ma][na][0], acc[ma][na][1]));
            m1 = fmaxf(m1, fmaxf(acc[ma][na][2], acc[ma][na][3]));
        }
        m0 = fmaxf(m0, __shfl_xor_sync(~0u, m0, 1));
        m0 = fmaxf(m0, __shfl_xor_sync(~0u, m0, 2));
        m1 = fmaxf(m1, __shfl_xor_sync(~0u, m1, 1));
        m1 = fmaxf(m1, __shfl_xor_sync(~0u, m1, 2));
        if (tig == 0) {
            redMax[wm * 32 + ma * 16 + g][wn] = m0;
            redMax[wm * 32 + ma * 16 + g + 8][wn] = m1;
        }
    }
    __syncthreads();
#pragma unroll
    for (int ma = 0; ma < 2; ma++)
#pragma unroll
        for (int h = 0; h < 2; h++) {
            int row = wm * 32 + ma * 16 + g + h * 8;
            float rm = fmaxf(fmaxf(redMax[row][0], redMax[row][1]),
                             fmaxf(redMax[row][2], redMax[row][3]));
            float s = 0.f;
#pragma unroll
            for (int na = 0; na < 4; na++) {
                s += __expf(acc[ma][na][h * 2] - rm);
                s += __expf(acc[ma][na][h * 2 + 1] - rm);
            }
            s += __shfl_xor_sync(~0u, s, 1);
            s += __shfl_xor_sync(~0u, s, 2);
            if (tig == 0) redSum[row][wn] = s;
        }
    __syncthreads();
    if (tid < 64) {
        float rm = fmaxf(fmaxf(redMax[tid][0], redMax[tid][1]),
                         fmaxf(redMax[tid][2], redMax[tid][3]));
        float s = redSum[tid][0] + redSum[tid][1] + redSum[tid][2] + redSum[tid][3];
        pmax[tid * 512 + blockIdx.x] = rm;
        psum[tid * 512 + blockIdx.x] = s;
    }
}

// ---------------- attn logits reduce + softmax over L=512 ----------------
__global__ void k_attn_softmax(const float* __restrict__ part, const float* __restrict__ bias,
                               float* __restrict__ wout) {
    int b = blockIdx.x;
    int l = threadIdx.x;
    float v = bias[l];
#pragma unroll
    for (int s = 0; s < 16; s++) v += part[((size_t)s * BB + b) * LL + l];

    __shared__ float red[32];
    float m = v;
#pragma unroll
    for (int o = 16; o > 0; o >>= 1) m = fmaxf(m, __shfl_xor_sync(~0u, m, o));
    if ((threadIdx.x & 31) == 0) red[threadIdx.x >> 5] = m;
    __syncthreads();
    if (threadIdx.x < 32) {
        float t = (threadIdx.x < 16) ? red[threadIdx.x] : -1e30f;
#pragma unroll
        for (int o = 8; o > 0; o >>= 1) t = fmaxf(t, __shfl_xor_sync(~0u, t, o));
        if (threadIdx.x == 0) red[0] = t;
    }
    __syncthreads();
    float rowmax = red[0];
    __syncthreads();
    float e = expf(v - rowmax);
    float ssum = e;
#pragma unroll
    for (int o = 16; o > 0; o >>= 1) ssum += __shfl_xor_sync(~0u, ssum, o);
    if ((threadIdx.x & 31) == 0) red[threadIdx.x >> 5] = ssum;
    __syncthreads();
    if (threadIdx.x < 32) {
        float t = (threadIdx.x < 16) ? red[threadIdx.x] : 0.f;
#pragma unroll
        for (int o = 8; o > 0; o >>= 1) t += __shfl_xor_sync(~0u, t, o);
        if (threadIdx.x == 0) red[0] = t;
    }
    __syncthreads();
    wout[b * LL + l] = e / red[0];
}

// ---------------- attn context partials: 32 slices of 16 L-rows ----------------
__global__ void k_attnapp_part(const float* __restrict__ w, const float* __restrict__ enc,
                               float* __restrict__ part) {
    int s = blockIdx.x;      // 32 slices
    int b = blockIdx.y;
    int d4 = threadIdx.x;
    __shared__ float ws[16];
    if (threadIdx.x < 16) ws[threadIdx.x] = w[b * LL + s * 16 + threadIdx.x];
    __syncthreads();
    const float4* ep = reinterpret_cast<const float4*>(enc + (size_t)b * LL * HH + (size_t)s * 16 * HH) + d4;
    float4 acc = make_float4(0.f, 0.f, 0.f, 0.f);
#pragma unroll
    for (int l = 0; l < 16; l++) {
        float4 v = __ldcs(ep + l * (HH / 4));
        float c = ws[l];
        acc.x += c * v.x; acc.y += c * v.y; acc.z += c * v.z; acc.w += c * v.w;
    }
    reinterpret_cast<float4*>(part + ((size_t)s * BB + b) * HH)[d4] = acc;
}

// ---------------- attnred v2: 256 blocks x 256 thr; 4 slice-groups x 64 outputs/block ----------------
__global__ void k_attnred(const float4* __restrict__ part, float4* __restrict__ out) {
    __shared__ float4 red[4][64];
    int o = blockIdx.x * 64 + (threadIdx.x & 63);    // output index (16384 total)
    int grp = threadIdx.x >> 6;                      // 0..3, handles slices grp*8..grp*8+7
    float4 v = make_float4(0.f, 0.f, 0.f, 0.f);
#pragma unroll
    for (int s = 0; s < 8; s++) {
        float4 p = part[(size_t)(grp * 8 + s) * 16384 + o];
        v.x += p.x; v.y += p.y; v.z += p.z; v.w += p.w;
    }
    red[grp][threadIdx.x & 63] = v;
    __syncthreads();
    if (threadIdx.x < 64) {
        float4 a = red[0][threadIdx.x], b = red[1][threadIdx.x];
        float4 c = red[2][threadIdx.x], d = red[3][threadIdx.x];
        out[o] = make_float4(a.x + b.x + c.x + d.x, a.y + b.y + c.y + d.y,
                             a.z + b.z + c.z + d.z, a.w + b.w + c.w + d.w);
    }
}

// ---------------- combine reduce + bias + relu (float4) ----------------
__global__ void k_combrelu(const float4* __restrict__ part, const float4* __restrict__ bias,
                           float4* __restrict__ out) {
    int idx = blockIdx.x * 256 + threadIdx.x;   // 16384
    float4 b = bias[idx & 255];
    float4 v = b;
#pragma unroll
    for (int s = 0; s < 16; s++) {
        float4 p = part[(size_t)s * 16384 + idx];
        v.x += p.x; v.y += p.y; v.z += p.z; v.w += p.w;
    }
    out[idx] = make_float4(fmaxf(v.x, 0.f), fmaxf(v.y, 0.f), fmaxf(v.z, 0.f), fmaxf(v.w, 0.f));
}

// ---------------- GRU gates (float4, split 4) ----------------
__global__ void k_gru(const float4* __restrict__ pgi, const float4* __restrict__ pgh,
                      const float4* __restrict__ bih, const float4* __restrict__ bhh,
                      const float4* __restrict__ hidden, float4* __restrict__ newh) {
    int idx = blockIdx.x * 256 + threadIdx.x;   // 16384
    int b = idx >> 8;
    int h4 = idx & 255;
    float4 ir = bih[h4], iz = bih[256 + h4], in_ = bih[512 + h4];
    float4 hr = bhh[h4], hz = bhh[256 + h4], hn = bhh[512 + h4];
#pragma unroll
    for (int s = 0; s < 4; s++) {
        size_t base = (size_t)(s * BB + b) * 768;
        float4 p;
        p = pgi[base + h4];        ir.x += p.x; ir.y += p.y; ir.z += p.z; ir.w += p.w;
        p = pgi[base + 256 + h4];  iz.x += p.x; iz.y += p.y; iz.z += p.z; iz.w += p.w;
        p = pgi[base + 512 + h4];  in_.x += p.x; in_.y += p.y; in_.z += p.z; in_.w += p.w;
        p = pgh[base + h4];        hr.x += p.x; hr.y += p.y; hr.z += p.z; hr.w += p.w;
        p = pgh[base + 256 + h4];  hz.x += p.x; hz.y += p.y; hz.z += p.z; hz.w += p.w;
        p = pgh[base + 512 + h4];  hn.x += p.x; hn.y += p.y; hn.z += p.z; hn.w += p.w;
    }
    float4 hd = hidden[idx];
    float4 o;
    {
        float r = 1.f / (1.f + expf(-(ir.x + hr.x)));
        float z = 1.f / (1.f + expf(-(iz.x + hz.x)));
        float n = tanhf(in_.x + r * hn.x);
        o.x = (1.f - z) * n + z * hd.x;
    }
    {
        float r = 1.f / (1.f + expf(-(ir.y + hr.y)));
        float z = 1.f / (1.f + expf(-(iz.y + hz.y)));
        float n = tanhf(in_.y + r * hn.y);
        o.y = (1.f - z) * n + z * hd.y;
    }
    {
        float r = 1.f / (1.f + expf(-(ir.z + hr.z)));
        float z = 1.f / (1.f + expf(-(iz.z + hz.z)));
        float n = tanhf(in_.z + r * hn.z);
        o.z = (1.f - z) * n + z * hd.z;
    }
    {
        float r = 1.f / (1.f + expf(-(ir.w + hr.w)));
        float z = 1.f / (1.f + expf(-(iz.w + hz.w)));
        float n = tanhf(in_.w + r * hn.w);
        o.w = (1.f - z) * n + z * hd.w;
    }
    newh[idx] = o;
}

// ---------------- lsm combine + write ----------------
__global__ void k_lsm_comb(const float* __restrict__ pmax, const float* __restrict__ psum,
                           float* __restrict__ lse) {
    int row = blockIdx.x;
    __shared__ float red[32];
    float m = -1e30f;
    for (int c = threadIdx.x; c < NBLK_OUT; c += 128) m = fmaxf(m, pmax[row * 512 + c]);
#pragma unroll
    for (int o = 16; o > 0; o >>= 1) m = fmaxf(m, __shfl_xor_sync(~0u, m, o));
    if ((threadIdx.x & 31) == 0) red[threadIdx.x >> 5] = m;
    __syncthreads();
    if (threadIdx.x < 32) {
        float t = (threadIdx.x < 4) ? red[threadIdx.x] : -1e30f;
#pragma unroll
        for (int o = 2; o > 0; o >>= 1) t = fmaxf(t, __shfl_xor_sync(~0u, t, o));
        if (threadIdx.x == 0) red[0] = t;
    }
    __syncthreads();
    float M = red[0];
    __syncthreads();
    float s = 0.f;
    for (int c = threadIdx.x; c < NBLK_OUT; c += 128)
        s += psum[row * 512 + c] * __expf(pmax[row * 512 + c] - M);
#pragma unroll
    for (int o = 16; o > 0; o >>= 1) s += __shfl_xor_sync(~0u, s, o);
    if ((threadIdx.x & 31) == 0) red[threadIdx.x >> 5] = s;
    __syncthreads();
    if (threadIdx.x < 32) {
        float t = (threadIdx.x < 4) ? red[threadIdx.x] : 0.f;
#pragma unroll
        for (int o = 2; o > 0; o >>= 1) t += __shfl_xor_sync(~0u, t, o);
        if (threadIdx.x == 0) lse[row] = M + logf(t);
    }
}

// flat float4 over the whole [64*VV] region (base is aligned, 64*VV % 4 == 0).
__global__ void k_lsm_write(float* __restrict__ out, const float* __restrict__ lse) {
    const int TOT4 = (BB * VV) >> 2;            // 804112
    int i4 = blockIdx.x * 256 + threadIdx.x;
    if (i4 >= TOT4) return;
    int e0 = i4 * 4;
    int b0 = e0 / VV;
    int b3 = (e0 + 3) / VV;
    float4* p = reinterpret_cast<float4*>(out) + i4;
    float4 v = *p;
    if (b0 == b3) {
        float L = lse[b0];
        v.x -= L; v.y -= L; v.z -= L; v.w -= L;
    } else {
        v.x -= lse[e0 / VV];
        v.y -= lse[(e0 + 1) / VV];
        v.z -= lse[(e0 + 2) / VV];
        v.w -= lse[(e0 + 3) / VV];
    }
    *p = v;
}

// ---------------- launch ----------------
extern "C" void kernel_launch(void* const* d_in, const int* in_sizes, int n_in,
                              void* d_out, int out_size) {
    const int*   ids    = (const int*)  d_in[0];
    const float* hidden = (const float*)d_in[1];
    const float* enc    = (const float*)d_in[2];
    const float* embW   = (const float*)d_in[3];
    const float* attnW  = (const float*)d_in[4];
    const float* attnb  = (const float*)d_in[5];
    const float* combW  = (const float*)d_in[6];
    const float* combb  = (const float*)d_in[7];
    const float* Wih    = (const float*)d_in[8];
    const float* Whh    = (const float*)d_in[9];
    const float* bih    = (const float*)d_in[10];
    const float* bhh    = (const float*)d_in[11];
    const float* outW   = (const float*)d_in[12];
    const float* outb   = (const float*)d_in[13];

    float* out  = (float*)d_out;
    float* newh = out + (size_t)BB * VV;

    float *p_attnw, *p_attnapp, *p_x, *p_pa, *p_pb, *p_pmax, *p_psum, *p_lse;
    cudaGetSymbolAddress((void**)&p_attnw, g_attnw);
    cudaGetSymbolAddress((void**)&p_attnapp, g_attnapp);
    cudaGetSymbolAddress((void**)&p_x, g_x);
    cudaGetSymbolAddress((void**)&p_pa, g_partA);
    cudaGetSymbolAddress((void**)&p_pb, g_partB);
    cudaGetSymbolAddress((void**)&p_pmax, g_pmax);
    cudaGetSymbolAddress((void**)&p_psum, g_psum);
    cudaGetSymbolAddress((void**)&p_lse, g_lse);

    // 1. attn logits: cat(gather(emb), hidden) @ attn_W^T, split-K 16
    gemm_bf16s<<<dim3(4, 16, 1), 256>>>(embW, hidden, ids, EE, EE + HH, attnW,
                                        p_pa, LL, 128, nullptr, nullptr, nullptr);

    // 2. reduce + bias + softmax over L
    k_attn_softmax<<<BB, 512>>>(p_pa, attnb, p_attnw);

    // 3. attention context (32 L-slices + parallel reduce)
    k_attnapp_part<<<dim3(32, BB), 256>>>(p_attnw, enc, p_pb);
    k_attnred<<<256, 256>>>((const float4*)p_pb, (float4*)p_attnapp);

    // 4. combine: cat(gather(emb), attn_applied) @ comb_W^T, split-K 16
    gemm_bf16s<<<dim3(8, 16, 1), 256>>>(embW, p_attnapp, ids, EE, EE + HH, combW,
                                        p_pa, EE, 128, nullptr, nullptr, nullptr);
    k_combrelu<<<64, 256>>>((const float4*)p_pa, (const float4*)combb, (float4*)p_x);

    // 5. GRU gi (z=0) and gh (z=1), split-K 4
    gemm_bf16s<<<dim3(24, 4, 2), 256>>>(p_x, nullptr, nullptr, HH, HH, Wih,
                                        p_pa, 3 * HH, 256,
                                        hidden, Whh, p_pb);
    k_gru<<<64, 256>>>((const float4*)p_pa, (const float4*)p_pb,
                       (const float4*)bih, (const float4*)bhh,
                       (const float4*)hidden, (float4*)newh);

    // 6. output projection (2-MMA split-A bf16, 2 blocks/SM) + fused lsm partials
    k_outproj<<<NBLK_OUT, 256>>>(newh, outW, outb, out, p_pmax, p_psum);

    // 7. lsm combine + write
    k_lsm_comb<<<BB, 128>>>(p_pmax, p_psum, p_lse);
    k_lsm_write<<<(BB * VV / 4 + 255) / 256, 256>>>(out, p_lse);
}

// round 10
// speedup vs baseline: 1.2545x; 1.0131x over previous
#include <cuda_runtime.h>
#include <math.h>
#include <stdint.h>

#define BB 64
#define EE 1024
#define HH 1024
#define LL 512
#define VV 50257
#define NBLK_OUT 393   // ceil(VV/128)

// ---------------- scratch (device globals, no allocation) ----------------
__device__ float g_attnw[BB * LL];
__device__ float g_attnapp[BB * HH];
__device__ float g_x[BB * EE];
__device__ float g_partA[16 * BB * EE];      // attn 16*64*512, comb 16*64*1024, gi 4*64*3072
__device__ float g_partB[16 * BB * EE];      // attnapp 16*64*1024; gh 4*64*3072
__device__ float g_pmax[64 * 512];
__device__ float g_psum[64 * 512];

// ---------------- helpers ----------------
__device__ __forceinline__ uint32_t pack_bf16(float lo, float hi) {
    uint32_t r;
    asm("cvt.rn.bf16x2.f32 %0, %1, %2;" : "=r"(r) : "f"(hi), "f"(lo));
    return r;
}
__device__ __forceinline__ int tile_off8(int row, int k) {
    int c = k >> 3;
    return (((row >> 3) << 3) + c) * 128 + (((row & 7) ^ c) << 4) + (k & 7) * 2;
}
__device__ __forceinline__ void split_store(char* hiP, char* loP, int off, float4 v) {
    uint32_t bx = __float_as_uint(v.x), by = __float_as_uint(v.y);
    uint32_t bz = __float_as_uint(v.z), bw = __float_as_uint(v.w);
    uint2 hi = make_uint2(__byte_perm(bx, by, 0x7632), __byte_perm(bz, bw, 0x7632));
    float lx = v.x - __uint_as_float(bx & 0xffff0000u);
    float ly = v.y - __uint_as_float(by & 0xffff0000u);
    float lz = v.z - __uint_as_float(bz & 0xffff0000u);
    float lw = v.w - __uint_as_float(bw & 0xffff0000u);
    uint2 lo = make_uint2(pack_bf16(lx, ly), pack_bf16(lz, lw));
    *reinterpret_cast<uint2*>(hiP + off) = hi;
    *reinterpret_cast<uint2*>(loP + off) = lo;
}
__device__ __forceinline__ void rn_store(char* P, int off, float4 v) {
    uint2 r = make_uint2(pack_bf16(v.x, v.y), pack_bf16(v.z, v.w));
    *reinterpret_cast<uint2*>(P + off) = r;
}

#define MMA_BF16(ac, a, b0, b1)                                                   \
    asm volatile("mma.sync.aligned.m16n8k16.row.col.f32.bf16.bf16.f32 "           \
                 "{%0,%1,%2,%3}, {%4,%5,%6,%7}, {%8,%9}, {%0,%1,%2,%3};"          \
                 : "+f"((ac)[0]), "+f"((ac)[1]), "+f"((ac)[2]), "+f"((ac)[3])     \
                 : "r"((a)[0]), "r"((a)[1]), "r"((a)[2]), "r"((a)[3]),            \
                   "r"(b0), "r"(b1))

// ================= split-bf16 tensor GEMM (split-K partials, 3-MMA) =================
__global__ __launch_bounds__(256) void gemm_bf16s(
    const float* __restrict__ A1, const float* __restrict__ A2,
    const int* __restrict__ gids, int K1, int K,
    const float* __restrict__ W, float* __restrict__ C, int N, int kChunk,
    const float* A1b, const float* Wb, float* Cb) {
    if (blockIdx.z == 1) { A1 = A1b; W = Wb; C = Cb; gids = nullptr; }

    __shared__ __align__(16) uint32_t smAhi[2048], smAlo[2048];
    __shared__ __align__(16) uint32_t smBhi[4096], smBlo[4096];

    const int tid = threadIdx.x;
    const int lane = tid & 31, wid = tid >> 5;
    const int wm = wid & 1, wn = wid >> 1;
    const int nBase = blockIdx.x * 128;
    const int kBase = blockIdx.y * kChunk;
    const int tiles = kChunk >> 6;

    uint32_t aHi = (uint32_t)__cvta_generic_to_shared(smAhi);
    uint32_t aLo = (uint32_t)__cvta_generic_to_shared(smAlo);
    uint32_t bHi = (uint32_t)__cvta_generic_to_shared(smBhi);
    uint32_t bLo = (uint32_t)__cvta_generic_to_shared(smBlo);

    int aAtom[2], aLowr[2];
#pragma unroll
    for (int ma = 0; ma < 2; ma++) {
        int row = wm * 32 + ma * 16 + ((lane >> 3) & 1) * 8 + (lane & 7);
        aAtom[ma] = (row >> 3) << 10;
        aLowr[ma] = row & 7;
    }
    const int aCbit = lane >> 4;
    int bAtom[4], bLowr[4];
    const int ll = lane & 15;
#pragma unroll
    for (int na = 0; na < 4; na++) {
        int n = wn * 32 + na * 8 + (ll & 7);
        bAtom[na] = (n >> 3) << 10;
        bLowr[na] = n & 7;
    }
    const int bCbit = ll >> 3;

    float acc[2][4][4];
#pragma unroll
    for (int i = 0; i < 2; i++)
#pragma unroll
        for (int j = 0; j < 4; j++)
#pragma unroll
            for (int q = 0; q < 4; q++) acc[i][j][q] = 0.f;

    float4 ra[4], rb[8];
    const int arow = tid >> 4, ac4 = tid & 15;

    auto loadA = [&](int k0) {
#pragma unroll
        for (int s = 0; s < 4; s++) {
            int row = arow + 16 * s;
            int k = k0 + ac4 * 4;
            const float* rp;
            if (k < K1) rp = (gids ? A1 + (size_t)gids[row] * K1 : A1 + (size_t)row * K1) + k;
            else        rp = A2 + (size_t)row * (K - K1) + (k - K1);
            ra[s] = *reinterpret_cast<const float4*>(rp);
        }
    };
    auto loadB = [&](int k0) {
#pragma unroll
        for (int s = 0; s < 8; s++)
            rb[s] = __ldcs(reinterpret_cast<const float4*>(
                W + (size_t)(nBase + arow + 16 * s) * K + k0 + ac4 * 4));
    };

    loadA(kBase);
    loadB(kBase);

    for (int kt = 0; kt < tiles; kt++) {
        __syncthreads();
#pragma unroll
        for (int s = 0; s < 4; s++)
            split_store((char*)smAhi, (char*)smAlo, tile_off8(arow + 16 * s, ac4 * 4), ra[s]);
#pragma unroll
        for (int s = 0; s < 8; s++)
            split_store((char*)smBhi, (char*)smBlo, tile_off8(arow + 16 * s, ac4 * 4), rb[s]);
        __syncthreads();
        if (kt + 1 < tiles) {
            loadA(kBase + (kt + 1) * 64);
            loadB(kBase + (kt + 1) * 64);
        }
#pragma unroll
        for (int ka = 0; ka < 4; ka++) {
            uint32_t afh[2][4], afl[2][4], bfh[4][2], bfl[4][2];
#pragma unroll
            for (int ma = 0; ma < 2; ma++) {
                int c = ka * 2 + aCbit;
                uint32_t off = aAtom[ma] + c * 128 + ((aLowr[ma] ^ c) << 4);
                asm volatile("ldmatrix.sync.aligned.m8n8.x4.shared.b16 {%0,%1,%2,%3}, [%4];"
                             : "=r"(afh[ma][0]), "=r"(afh[ma][1]), "=r"(afh[ma][2]), "=r"(afh[ma][3])
                             : "r"(aHi + off));
                asm volatile("ldmatrix.sync.aligned.m8n8.x4.shared.b16 {%0,%1,%2,%3}, [%4];"
                             : "=r"(afl[ma][0]), "=r"(afl[ma][1]), "=r"(afl[ma][2]), "=r"(afl[ma][3])
                             : "r"(aLo + off));
            }
#pragma unroll
            for (int na = 0; na < 4; na++) {
                int c = ka * 2 + bCbit;
                uint32_t off = bAtom[na] + c * 128 + ((bLowr[na] ^ c) << 4);
                asm volatile("ldmatrix.sync.aligned.m8n8.x2.shared.b16 {%0,%1}, [%2];"
                             : "=r"(bfh[na][0]), "=r"(bfh[na][1]) : "r"(bHi + off));
                asm volatile("ldmatrix.sync.aligned.m8n8.x2.shared.b16 {%0,%1}, [%2];"
                             : "=r"(bfl[na][0]), "=r"(bfl[na][1]) : "r"(bLo + off));
            }
#pragma unroll
            for (int ma = 0; ma < 2; ma++)
#pragma unroll
                for (int na = 0; na < 4; na++) {
                    MMA_BF16(acc[ma][na], afh[ma], bfh[na][0], bfh[na][1]);
                    MMA_BF16(acc[ma][na], afh[ma], bfl[na][0], bfl[na][1]);
                    MMA_BF16(acc[ma][na], afl[ma], bfh[na][0], bfh[na][1]);
                }
        }
    }

    float* Cout = C + (size_t)blockIdx.y * 64 * N;
    int g = lane >> 2, tig = lane & 3;
#pragma unroll
    for (int ma = 0; ma < 2; ma++)
#pragma unroll
        for (int na = 0; na < 4; na++) {
            int col = nBase + wn * 32 + na * 8 + tig * 2;
            int r0 = wm * 32 + ma * 16 + g;
            *reinterpret_cast<float2*>(Cout + (size_t)r0 * N + col) =
                make_float2(acc[ma][na][0], acc[ma][na][1]);
            *reinterpret_cast<float2*>(Cout + (size_t)(r0 + 8) * N + col) =
                make_float2(acc[ma][na][2], acc[ma][na][3]);
        }
}

// ================= fat output GEMM: 2-MMA (A split, W rn) + bias + fused lsm =================
__global__ __launch_bounds__(256, 2) void k_outproj(const float* __restrict__ A,
                                                    const float* __restrict__ W,
                                                    const float* __restrict__ bias,
                                                    float* __restrict__ C,
                                                    float* __restrict__ pmax,
                                                    float* __restrict__ psum) {
    __shared__ __align__(16) uint32_t smAhi[2048], smAlo[2048];
    __shared__ __align__(16) uint32_t smB[4096];
    __shared__ float redMax[64][4];
    __shared__ float redSum[64][4];

    const int tid = threadIdx.x;
    const int lane = tid & 31, wid = tid >> 5;
    const int wm = wid & 1, wn = wid >> 1;
    const int nBase = blockIdx.x * 128;

    uint32_t aHi = (uint32_t)__cvta_generic_to_shared(smAhi);
    uint32_t aLo = (uint32_t)__cvta_generic_to_shared(smAlo);
    uint32_t bSm = (uint32_t)__cvta_generic_to_shared(smB);

    int aAtom[2], aLowr[2];
#pragma unroll
    for (int ma = 0; ma < 2; ma++) {
        int row = wm * 32 + ma * 16 + ((lane >> 3) & 1) * 8 + (lane & 7);
        aAtom[ma] = (row >> 3) << 10;
        aLowr[ma] = row & 7;
    }
    const int aCbit = lane >> 4;
    int bAtom[4], bLowr[4];
    const int ll = lane & 15;
#pragma unroll
    for (int na = 0; na < 4; na++) {
        int n = wn * 32 + na * 8 + (ll & 7);
        bAtom[na] = (n >> 3) << 10;
        bLowr[na] = n & 7;
    }
    const int bCbit = ll >> 3;

    float acc[2][4][4];
#pragma unroll
    for (int i = 0; i < 2; i++)
#pragma unroll
        for (int j = 0; j < 4; j++)
#pragma unroll
            for (int q = 0; q < 4; q++) acc[i][j][q] = 0.f;

    float4 ra[4], rb[8];
    const int arow = tid >> 4, ac4 = tid & 15;

    auto loadA = [&](int k0) {
#pragma unroll
        for (int s = 0; s < 4; s++)
            ra[s] = *reinterpret_cast<const float4*>(A + (size_t)(arow + 16 * s) * 1024 + k0 + ac4 * 4);
    };
    auto loadB = [&](int k0) {
#pragma unroll
        for (int s = 0; s < 8; s++) {
            int ng = nBase + arow + 16 * s;
            if (ng < VV)
                rb[s] = __ldcs(reinterpret_cast<const float4*>(W + (size_t)ng * 1024 + k0 + ac4 * 4));
            else
                rb[s] = make_float4(0.f, 0.f, 0.f, 0.f);
        }
    };

    loadA(0);
    loadB(0);

    for (int kt = 0; kt < 16; kt++) {
        __syncthreads();
#pragma unroll
        for (int s = 0; s < 4; s++)
            split_store((char*)smAhi, (char*)smAlo, tile_off8(arow + 16 * s, ac4 * 4), ra[s]);
#pragma unroll
        for (int s = 0; s < 8; s++)
            rn_store((char*)smB, tile_off8(arow + 16 * s, ac4 * 4), rb[s]);
        __syncthreads();
        if (kt + 1 < 16) {
            loadA((kt + 1) * 64);
            loadB((kt + 1) * 64);
        }
#pragma unroll
        for (int ka = 0; ka < 4; ka++) {
            uint32_t afh[2][4], afl[2][4], bf[4][2];
#pragma unroll
            for (int ma = 0; ma < 2; ma++) {
                int c = ka * 2 + aCbit;
                uint32_t off = aAtom[ma] + c * 128 + ((aLowr[ma] ^ c) << 4);
                asm volatile("ldmatrix.sync.aligned.m8n8.x4.shared.b16 {%0,%1,%2,%3}, [%4];"
                             : "=r"(afh[ma][0]), "=r"(afh[ma][1]), "=r"(afh[ma][2]), "=r"(afh[ma][3])
                             : "r"(aHi + off));
                asm volatile("ldmatrix.sync.aligned.m8n8.x4.shared.b16 {%0,%1,%2,%3}, [%4];"
                             : "=r"(afl[ma][0]), "=r"(afl[ma][1]), "=r"(afl[ma][2]), "=r"(afl[ma][3])
                             : "r"(aLo + off));
            }
#pragma unroll
            for (int na = 0; na < 4; na++) {
                int c = ka * 2 + bCbit;
                uint32_t off = bAtom[na] + c * 128 + ((bLowr[na] ^ c) << 4);
                asm volatile("ldmatrix.sync.aligned.m8n8.x2.shared.b16 {%0,%1}, [%2];"
                             : "=r"(bf[na][0]), "=r"(bf[na][1]) : "r"(bSm + off));
            }
#pragma unroll
            for (int ma = 0; ma < 2; ma++)
#pragma unroll
                for (int na = 0; na < 4; na++) {
                    MMA_BF16(acc[ma][na], afh[ma], bf[na][0], bf[na][1]);
                    MMA_BF16(acc[ma][na], afl[ma], bf[na][0], bf[na][1]);
                }
        }
    }

    int g = lane >> 2, tig = lane & 3;
#pragma unroll
    for (int ma = 0; ma < 2; ma++)
#pragma unroll
        for (int na = 0; na < 4; na++) {
            int col = nBase + wn * 32 + na * 8 + tig * 2;
            int r0 = wm * 32 + ma * 16 + g;
            if (col < VV) {
                float b0 = bias[col];
                acc[ma][na][0] += b0; acc[ma][na][2] += b0;
                C[(size_t)r0 * VV + col]       = acc[ma][na][0];
                C[(size_t)(r0 + 8) * VV + col] = acc[ma][na][2];
            } else { acc[ma][na][0] = -1e30f; acc[ma][na][2] = -1e30f; }
            if (col + 1 < VV) {
                float b1 = bias[col + 1];
                acc[ma][na][1] += b1; acc[ma][na][3] += b1;
                C[(size_t)r0 * VV + col + 1]       = acc[ma][na][1];
                C[(size_t)(r0 + 8) * VV + col + 1] = acc[ma][na][3];
            } else { acc[ma][na][1] = -1e30f; acc[ma][na][3] = -1e30f; }
        }

#pragma unroll
    for (int ma = 0; ma < 2; ma++) {
        float m0 = -1e30f, m1 = -1e30f;
#pragma unroll
        for (int na = 0; na < 4; na++) {
            m0 = fmaxf(m0, fmaxf(acc[ma][na][0], acc[ma][na][1]));
            m1 = fmaxf(m1, fmaxf(acc[ma][na][2], acc[ma][na][3]));
        }
        m0 = fmaxf(m0, __shfl_xor_sync(~0u, m0, 1));
        m0 = fmaxf(m0, __shfl_xor_sync(~0u, m0, 2));
        m1 = fmaxf(m1, __shfl_xor_sync(~0u, m1, 1));
        m1 = fmaxf(m1, __shfl_xor_sync(~0u, m1, 2));
        if (tig == 0) {
            redMax[wm * 32 + ma * 16 + g][wn] = m0;
            redMax[wm * 32 + ma * 16 + g + 8][wn] = m1;
        }
    }
    __syncthreads();
#pragma unroll
    for (int ma = 0; ma < 2; ma++)
#pragma unroll
        for (int h = 0; h < 2; h++) {
            int row = wm * 32 + ma * 16 + g + h * 8;
            float rm = fmaxf(fmaxf(redMax[row][0], redMax[row][1]),
                             fmaxf(redMax[row][2], redMax[row][3]));
            float s = 0.f;
#pragma unroll
            for (int na = 0; na < 4; na++) {
                s += __expf(acc[ma][na][h * 2] - rm);
                s += __expf(acc[ma][na][h * 2 + 1] - rm);
            }
            s += __shfl_xor_sync(~0u, s, 1);
            s += __shfl_xor_sync(~0u, s, 2);
            if (tig == 0) redSum[row][wn] = s;
        }
    __syncthreads();
    if (tid < 64) {
        float rm = fmaxf(fmaxf(redMax[tid][0], redMax[tid][1]),
                         fmaxf(redMax[tid][2], redMax[tid][3]));
        float s = redSum[tid][0] + redSum[tid][1] + redSum[tid][2] + redSum[tid][3];
        pmax[tid * 512 + blockIdx.x] = rm;
        psum[tid * 512 + blockIdx.x] = s;
    }
}

// ---------------- attn logits reduce + softmax over L=512 ----------------
__global__ void k_attn_softmax(const float* __restrict__ part, const float* __restrict__ bias,
                               float* __restrict__ wout) {
    int b = blockIdx.x;
    int l = threadIdx.x;
    float v = bias[l];
#pragma unroll
    for (int s = 0; s < 16; s++) v += part[((size_t)s * BB + b) * LL + l];

    __shared__ float red[32];
    float m = v;
#pragma unroll
    for (int o = 16; o > 0; o >>= 1) m = fmaxf(m, __shfl_xor_sync(~0u, m, o));
    if ((threadIdx.x & 31) == 0) red[threadIdx.x >> 5] = m;
    __syncthreads();
    if (threadIdx.x < 32) {
        float t = (threadIdx.x < 16) ? red[threadIdx.x] : -1e30f;
#pragma unroll
        for (int o = 8; o > 0; o >>= 1) t = fmaxf(t, __shfl_xor_sync(~0u, t, o));
        if (threadIdx.x == 0) red[0] = t;
    }
    __syncthreads();
    float rowmax = red[0];
    __syncthreads();
    float e = expf(v - rowmax);
    float ssum = e;
#pragma unroll
    for (int o = 16; o > 0; o >>= 1) ssum += __shfl_xor_sync(~0u, ssum, o);
    if ((threadIdx.x & 31) == 0) red[threadIdx.x >> 5] = ssum;
    __syncthreads();
    if (threadIdx.x < 32) {
        float t = (threadIdx.x < 16) ? red[threadIdx.x] : 0.f;
#pragma unroll
        for (int o = 8; o > 0; o >>= 1) t += __shfl_xor_sync(~0u, t, o);
        if (threadIdx.x == 0) red[0] = t;
    }
    __syncthreads();
    wout[b * LL + l] = e / red[0];
}

// ---------------- attn context partials: 16 slices of 32 L-rows ----------------
__global__ void k_attnapp_part(const float* __restrict__ w, const float* __restrict__ enc,
                               float* __restrict__ part) {
    int s = blockIdx.x;      // 16 slices
    int b = blockIdx.y;
    int d4 = threadIdx.x;
    __shared__ float ws[32];
    if (threadIdx.x < 32) ws[threadIdx.x] = w[b * LL + s * 32 + threadIdx.x];
    __syncthreads();
    const float4* ep = reinterpret_cast<const float4*>(enc + (size_t)b * LL * HH + (size_t)s * 32 * HH) + d4;
    float4 acc = make_float4(0.f, 0.f, 0.f, 0.f);
#pragma unroll 8
    for (int l = 0; l < 32; l++) {
        float4 v = __ldcs(ep + l * (HH / 4));
        float c = ws[l];
        acc.x += c * v.x; acc.y += c * v.y; acc.z += c * v.z; acc.w += c * v.w;
    }
    reinterpret_cast<float4*>(part + ((size_t)s * BB + b) * HH)[d4] = acc;
}

// ---------------- attnred: 256 blocks x 256 thr; 4 groups x 4 slices, 64 outputs ----------------
__global__ void k_attnred(const float4* __restrict__ part, float4* __restrict__ out) {
    __shared__ float4 red[4][64];
    int o = blockIdx.x * 64 + (threadIdx.x & 63);    // output index (16384 total)
    int grp = threadIdx.x >> 6;                      // 0..3, slices grp*4..grp*4+3
    float4 v = make_float4(0.f, 0.f, 0.f, 0.f);
#pragma unroll
    for (int s = 0; s < 4; s++) {
        float4 p = part[(size_t)(grp * 4 + s) * 16384 + o];
        v.x += p.x; v.y += p.y; v.z += p.z; v.w += p.w;
    }
    red[grp][threadIdx.x & 63] = v;
    __syncthreads();
    if (threadIdx.x < 64) {
        float4 a = red[0][threadIdx.x], b = red[1][threadIdx.x];
        float4 c = red[2][threadIdx.x], d = red[3][threadIdx.x];
        out[o] = make_float4(a.x + b.x + c.x + d.x, a.y + b.y + c.y + d.y,
                             a.z + b.z + c.z + d.z, a.w + b.w + c.w + d.w);
    }
}

// ---------------- combine reduce + bias + relu (float4) ----------------
__global__ void k_combrelu(const float4* __restrict__ part, const float4* __restrict__ bias,
                           float4* __restrict__ out) {
    int idx = blockIdx.x * 256 + threadIdx.x;   // 16384
    float4 b = bias[idx & 255];
    float4 v = b;
#pragma unroll
    for (int s = 0; s < 16; s++) {
        float4 p = part[(size_t)s * 16384 + idx];
        v.x += p.x; v.y += p.y; v.z += p.z; v.w += p.w;
    }
    out[idx] = make_float4(fmaxf(v.x, 0.f), fmaxf(v.y, 0.f), fmaxf(v.z, 0.f), fmaxf(v.w, 0.f));
}

// ---------------- GRU gates (float4, split 4) ----------------
__global__ void k_gru(const float4* __restrict__ pgi, const float4* __restrict__ pgh,
                      const float4* __restrict__ bih, const float4* __restrict__ bhh,
                      const float4* __restrict__ hidden, float4* __restrict__ newh) {
    int idx = blockIdx.x * 256 + threadIdx.x;   // 16384
    int b = idx >> 8;
    int h4 = idx & 255;
    float4 ir = bih[h4], iz = bih[256 + h4], in_ = bih[512 + h4];
    float4 hr = bhh[h4], hz = bhh[256 + h4], hn = bhh[512 + h4];
#pragma unroll
    for (int s = 0; s < 4; s++) {
        size_t base = (size_t)(s * BB + b) * 768;
        float4 p;
        p = pgi[base + h4];        ir.x += p.x; ir.y += p.y; ir.z += p.z; ir.w += p.w;
        p = pgi[base + 256 + h4];  iz.x += p.x; iz.y += p.y; iz.z += p.z; iz.w += p.w;
        p = pgi[base + 512 + h4];  in_.x += p.x; in_.y += p.y; in_.z += p.z; in_.w += p.w;
        p = pgh[base + h4];        hr.x += p.x; hr.y += p.y; hr.z += p.z; hr.w += p.w;
        p = pgh[base + 256 + h4];  hz.x += p.x; hz.y += p.y; hz.z += p.z; hz.w += p.w;
        p = pgh[base + 512 + h4];  hn.x += p.x; hn.y += p.y; hn.z += p.z; hn.w += p.w;
    }
    float4 hd = hidden[idx];
    float4 o;
    {
        float r = 1.f / (1.f + expf(-(ir.x + hr.x)));
        float z = 1.f / (1.f + expf(-(iz.x + hz.x)));
        float n = tanhf(in_.x + r * hn.x);
        o.x = (1.f - z) * n + z * hd.x;
    }
    {
        float r = 1.f / (1.f + expf(-(ir.y + hr.y)));
        float z = 1.f / (1.f + expf(-(iz.y + hz.y)));
        float n = tanhf(in_.y + r * hn.y);
        o.y = (1.f - z) * n + z * hd.y;
    }
    {
        float r = 1.f / (1.f + expf(-(ir.z + hr.z)));
        float z = 1.f / (1.f + expf(-(iz.z + hz.z)));
        float n = tanhf(in_.z + r * hn.z);
        o.z = (1.f - z) * n + z * hd.z;
    }
    {
        float r = 1.f / (1.f + expf(-(ir.w + hr.w)));
        float z = 1.f / (1.f + expf(-(iz.w + hz.w)));
        float n = tanhf(in_.w + r * hn.w);
        o.w = (1.f - z) * n + z * hd.w;
    }
    newh[idx] = o;
}

// ---------------- fused lsm: each block computes its row's lse, then subtracts ----------------
__global__ void k_lsm_write(float* __restrict__ out,
                            const float* __restrict__ pmax, const float* __restrict__ psum) {
    int c = blockIdx.x;          // 8 chunks
    int b = blockIdx.y;
    __shared__ float red[8];
    __shared__ float s_lse;

    // phase 1: row max over NBLK_OUT partials
    float m = -1e30f;
    for (int i = threadIdx.x; i < NBLK_OUT; i += 256) m = fmaxf(m, pmax[b * 512 + i]);
#pragma unroll
    for (int o = 16; o > 0; o >>= 1) m = fmaxf(m, __shfl_xor_sync(~0u, m, o));
    if ((threadIdx.x & 31) == 0) red[threadIdx.x >> 5] = m;
    __syncthreads();
    if (threadIdx.x == 0) {
        float t = red[0];
#pragma unroll
        for (int i = 1; i < 8; i++) t = fmaxf(t, red[i]);
        red[0] = t;
    }
    __syncthreads();
    float M = red[0];
    __syncthreads();
    // phase 2: sum
    float s = 0.f;
    for (int i = threadIdx.x; i < NBLK_OUT; i += 256)
        s += psum[b * 512 + i] * __expf(pmax[b * 512 + i] - M);
#pragma unroll
    for (int o = 16; o > 0; o >>= 1) s += __shfl_xor_sync(~0u, s, o);
    if ((threadIdx.x & 31) == 0) red[threadIdx.x >> 5] = s;
    __syncthreads();
    if (threadIdx.x == 0) {
        float t = 0.f;
#pragma unroll
        for (int i = 0; i < 8; i++) t += red[i];
        s_lse = M + logf(t);
    }
    __syncthreads();
    float L = s_lse;

    // phase 3: subtract over this block's chunk (scalar, always aligned)
    const int CH = (VV + 7) / 8;
    int start = c * CH;
    int end = min(start + CH, VV);
    float* row = out + (size_t)b * VV;
    for (int i = start + threadIdx.x; i < end; i += 256) row[i] -= L;
}

// ---------------- launch ----------------
extern "C" void kernel_launch(void* const* d_in, const int* in_sizes, int n_in,
                              void* d_out, int out_size) {
    const int*   ids    = (const int*)  d_in[0];
    const float* hidden = (const float*)d_in[1];
    const float* enc    = (const float*)d_in[2];
    const float* embW   = (const float*)d_in[3];
    const float* attnW  = (const float*)d_in[4];
    const float* attnb  = (const float*)d_in[5];
    const float* combW  = (const float*)d_in[6];
    const float* combb  = (const float*)d_in[7];
    const float* Wih    = (const float*)d_in[8];
    const float* Whh    = (const float*)d_in[9];
    const float* bih    = (const float*)d_in[10];
    const float* bhh    = (const float*)d_in[11];
    const float* outW   = (const float*)d_in[12];
    const float* outb   = (const float*)d_in[13];

    float* out  = (float*)d_out;
    float* newh = out + (size_t)BB * VV;

    float *p_attnw, *p_attnapp, *p_x, *p_pa, *p_pb, *p_pmax, *p_psum;
    cudaGetSymbolAddress((void**)&p_attnw, g_attnw);
    cudaGetSymbolAddress((void**)&p_attnapp, g_attnapp);
    cudaGetSymbolAddress((void**)&p_x, g_x);
    cudaGetSymbolAddress((void**)&p_pa, g_partA);
    cudaGetSymbolAddress((void**)&p_pb, g_partB);
    cudaGetSymbolAddress((void**)&p_pmax, g_pmax);
    cudaGetSymbolAddress((void**)&p_psum, g_psum);

    // 1. attn logits: cat(gather(emb), hidden) @ attn_W^T, split-K 16
    gemm_bf16s<<<dim3(4, 16, 1), 256>>>(embW, hidden, ids, EE, EE + HH, attnW,
                                        p_pa, LL, 128, nullptr, nullptr, nullptr);

    // 2. reduce + bias + softmax over L
    k_attn_softmax<<<BB, 512>>>(p_pa, attnb, p_attnw);

    // 3. attention context (16 L-slices + grouped reduce)
    k_attnapp_part<<<dim3(16, BB), 256>>>(p_attnw, enc, p_pb);
    k_attnred<<<256, 256>>>((const float4*)p_pb, (float4*)p_attnapp);

    // 4. combine: cat(gather(emb), attn_applied) @ comb_W^T, split-K 16
    gemm_bf16s<<<dim3(8, 16, 1), 256>>>(embW, p_attnapp, ids, EE, EE + HH, combW,
                                        p_pa, EE, 128, nullptr, nullptr, nullptr);
    k_combrelu<<<64, 256>>>((const float4*)p_pa, (const float4*)combb, (float4*)p_x);

    // 5. GRU gi (z=0) and gh (z=1), split-K 4
    gemm_bf16s<<<dim3(24, 4, 2), 256>>>(p_x, nullptr, nullptr, HH, HH, Wih,
                                        p_pa, 3 * HH, 256,
                                        hidden, Whh, p_pb);
    k_gru<<<64, 256>>>((const float4*)p_pa, (const float4*)p_pb,
                       (const float4*)bih, (const float4*)bhh,
                       (const float4*)hidden, (float4*)newh);

    // 6. output projection (2-MMA split-A bf16, 2 blocks/SM) + fused lsm partials
    k_outproj<<<NBLK_OUT, 256>>>(newh, outW, outb, out, p_pmax, p_psum);

    // 7. fused lse + subtract
    k_lsm_write<<<dim3(8, BB), 256>>>(out, p_pmax, p_psum);
}